// round 12
// baseline (speedup 1.0000x reference)
#include <cuda_runtime.h>
#include <cuda_bf16.h>
#include <math.h>

#define N_NODES 20000
#define N_EDGES 320000

// ---------------- scratch (device globals) ----------------------------------
__device__ __align__(16) float g_ys [N_NODES * 64];
__device__ __align__(16) float g_yv [N_NODES * 192];
__device__ __align__(16) float g_scs[N_NODES * 64];
__device__ __align__(16) float g_scv[N_NODES * 192];
__device__ __align__(16) float g_ns [N_NODES * 128];
__device__ __align__(16) float g_nv [N_NODES * 384];
__device__ __align__(16) float g_deg[N_NODES];

typedef unsigned long long ull;

// ---------------- helpers ----------------------------------------------------
__device__ __forceinline__ void red4(float* p, float x, float y, float z, float w) {
    asm volatile("red.global.add.v4.f32 [%0], {%1,%2,%3,%4};"
                 :: "l"(p), "f"(x), "f"(y), "f"(z), "f"(w) : "memory");
}
__device__ __forceinline__ float silu(float x) {
    return x * (1.0f / (1.0f + __expf(-x)));
}
__device__ __forceinline__ unsigned smem_u32(const void* p) {
    unsigned a;
    asm("{ .reg .u64 t; cvta.to.shared.u64 t, %1; cvt.u32.u64 %0, t; }"
        : "=r"(a) : "l"(p));
    return a;
}
__device__ __forceinline__ void split2(float a, float b, unsigned& hi, unsigned& lo) {
    __nv_bfloat162 H, L;
    H.x = __float2bfloat16(a);
    H.y = __float2bfloat16(b);
    L.x = __float2bfloat16(a - __bfloat162float(H.x));
    L.y = __float2bfloat16(b - __bfloat162float(H.y));
    hi = *(unsigned*)&H;
    lo = *(unsigned*)&L;
}
__device__ __forceinline__ void mma_bf16(float* c, const unsigned* a, const unsigned* b) {
    asm volatile(
        "mma.sync.aligned.m16n8k16.row.col.f32.bf16.bf16.f32 "
        "{%0,%1,%2,%3}, {%4,%5,%6,%7}, {%8,%9}, {%0,%1,%2,%3};"
        : "+f"(c[0]), "+f"(c[1]), "+f"(c[2]), "+f"(c[3])
        : "r"(a[0]), "r"(a[1]), "r"(a[2]), "r"(a[3]), "r"(b[0]), "r"(b[1]));
}
__device__ __forceinline__ void ldsm4(unsigned* r, unsigned addr) {
    asm volatile("ldmatrix.sync.aligned.m8n8.x4.shared.b16 {%0,%1,%2,%3}, [%4];"
                 : "=r"(r[0]), "=r"(r[1]), "=r"(r[2]), "=r"(r[3]) : "r"(addr));
}

// ---------------- K1: zero scratch + node input transforms (mma bf16x3) -----
#define K1_SX   0
#define K1_AHI  8224
#define K1_ALO  12832
#define K1_SMEM (17440 * 4)
__global__ __launch_bounds__(256, 2) void k_node_in(
    const float* __restrict__ nh,
    const float* __restrict__ w1s, const float* __restrict__ w1v,
    const float* __restrict__ wscs, const float* __restrict__ wscv)
{
    extern __shared__ float sm[];
    float* sX = sm + K1_SX;                              // [32][257]
    __nv_bfloat16* sAhi = (__nv_bfloat16*)(sm + K1_AHI); // [128][72]
    __nv_bfloat16* sAlo = (__nv_bfloat16*)(sm + K1_ALO);

    const int tid  = threadIdx.x;
    const int wid  = tid >> 5;
    const int lane = tid & 31;

    {
        int gi = blockIdx.x * blockDim.x + tid;
        int gstr = gridDim.x * blockDim.x;
        float4 z = make_float4(0.f, 0.f, 0.f, 0.f);
        for (int j = gi; j < N_NODES * 128 / 4; j += gstr) ((float4*)g_ns)[j] = z;
        for (int j = gi; j < N_NODES * 384 / 4; j += gstr) ((float4*)g_nv)[j] = z;
        for (int j = gi; j < N_NODES; j += gstr) g_deg[j] = 0.f;
    }

    unsigned BH[2][4][2][2], BL[2][4][2][2];
    {
        const float inv = 0.125f;
        const float* srcS = (wid < 4) ? w1s : wscs;
        const float* srcV = (wid < 4) ? w1v : wscv;
        const int nc = (wid & 3) * 16 + (lane >> 2);
#pragma unroll
        for (int sv = 0; sv < 2; sv++) {
            const float* src = sv ? srcV : srcS;
#pragma unroll
            for (int nt = 0; nt < 2; nt++) {
#pragma unroll
                for (int kt = 0; kt < 4; kt++) {
                    int k0 = kt * 16 + (lane & 3) * 2;
                    int nn = nc + nt * 8;
                    float x0 = src[k0 * 64 + nn] * inv;
                    float x1 = src[(k0 + 1) * 64 + nn] * inv;
                    split2(x0, x1, BH[sv][kt][nt][0], BL[sv][kt][nt][0]);
                    float x2 = src[(k0 + 8) * 64 + nn] * inv;
                    float x3 = src[(k0 + 9) * 64 + nn] * inv;
                    split2(x2, x3, BH[sv][kt][nt][1], BL[sv][kt][nt][1]);
                }
            }
        }
    }
    const unsigned laneoff =
        ((lane & 7) + ((lane >> 3) & 1) * 8) * 144 + (lane >> 4) * 16;
    const unsigned ahiU = smem_u32(sAhi);
    const unsigned aloU = smem_u32(sAlo);

    for (int t = blockIdx.x; t < N_NODES / 32; t += gridDim.x) {
        __syncthreads();
        const int n0 = t * 32;
        for (int i = tid; i < 32 * 256; i += 256) {
            int n = i >> 8, c = i & 255;
            sX[n * 257 + c] = nh[(n0 + n) * 256 + c];
        }
        __syncthreads();

        {
            const int r = tid >> 1;
            const int b = r >> 5;
            const float* base = sX + (r & 31) * 257;
            const int ch = (tid & 1) * 16;
#pragma unroll
            for (int c = 0; c < 16; c++) {
                int cp = ch + c;
                float x0, x1;
                if (b == 0) {
                    x0 = base[2 * cp];
                    x1 = base[2 * cp + 1];
                } else {
                    x0 = base[64 + (2 * cp) * 3 + (b - 1)];
                    x1 = base[64 + (2 * cp + 1) * 3 + (b - 1)];
                }
                unsigned hi, lo;
                split2(x0, x1, hi, lo);
                *(unsigned*)(sAhi + r * 72 + cp * 2) = hi;
                *(unsigned*)(sAlo + r * 72 + cp * 2) = lo;
            }
        }
        __syncthreads();

#pragma unroll
        for (int mt = 0; mt < 8; mt++) {
            const int sv = (mt < 2) ? 0 : 1;
            const unsigned rowb = (unsigned)(mt * 16 * 144) + laneoff;
            float C[2][4];
#pragma unroll
            for (int nt = 0; nt < 2; nt++)
#pragma unroll
                for (int i = 0; i < 4; i++) C[nt][i] = 0.f;
#pragma unroll
            for (int kt = 0; kt < 4; kt++) {
                unsigned Ah[4], Al[4];
                ldsm4(Ah, ahiU + rowb + kt * 32);
                ldsm4(Al, aloU + rowb + kt * 32);
#pragma unroll
                for (int nt = 0; nt < 2; nt++) {
                    mma_bf16(C[nt], Ah, BH[sv][kt][nt]);
                    mma_bf16(C[nt], Ah, BL[sv][kt][nt]);
                    mma_bf16(C[nt], Al, BH[sv][kt][nt]);
                }
            }
            const int b2 = mt >> 1;
            const int nA = n0 + (mt & 1) * 16 + (lane >> 2);
            const int nB = nA + 8;
#pragma unroll
            for (int nt = 0; nt < 2; nt++) {
                const int v = (wid & 3) * 16 + nt * 8 + (lane & 3) * 2;
                float* dstA;
                float* dstB;
                if (wid < 4) {
                    if (b2 == 0) { dstA = g_ys + nA * 64 + v; dstB = g_ys + nB * 64 + v; }
                    else {
                        dstA = g_yv + nA * 192 + (b2 - 1) * 64 + v;
                        dstB = g_yv + nB * 192 + (b2 - 1) * 64 + v;
                    }
                } else {
                    if (b2 == 0) { dstA = g_scs + nA * 64 + v; dstB = g_scs + nB * 64 + v; }
                    else {
                        dstA = g_scv + nA * 192 + (b2 - 1) * 64 + v;
                        dstB = g_scv + nB * 192 + (b2 - 1) * 64 + v;
                    }
                }
                *(float2*)dstA = make_float2(C[nt][0], C[nt][1]);
                *(float2*)dstB = make_float2(C[nt][2], C[nt][3]);
            }
        }
    }
}

// ---------------- K2: edge MLP (stages 2+3 on mma.sync) + TP + scatter ------
#define SM_W1   0        // 512
#define SM_W2HI 512      // 2304 (W2^T bf16 hi, [64 n][72 k])
#define SM_W2LO 2816     // 2304
#define SM_H1HI 5120     // 4608 ([128 e][72] bf16)
#define SM_H1LO 9728     // 4608
#define SM_AHI  14336    // 4608 (h2 tiles)
#define SM_ALO  18944    // 4608
#define SM_WT   23552    // 64*264 = 16896
#define SM_EA   40448    // 1024
#define SM_SH   41472    // 512
#define SM_SD   41984    // 256 ints
#define K2_SMEM (42240 * 4)

__global__ __launch_bounds__(512, 1) void k_edge(
    const float* __restrict__ ea, const float* __restrict__ esh,
    const int* __restrict__ ei,
    const float* __restrict__ fw1, const float* __restrict__ fw2,
    const float* __restrict__ fw3)
{
    extern __shared__ float sm[];
    float* sW1 = sm + SM_W1;
    __nv_bfloat16* sW2hi = (__nv_bfloat16*)(sm + SM_W2HI);
    __nv_bfloat16* sW2lo = (__nv_bfloat16*)(sm + SM_W2LO);
    __nv_bfloat16* sH1hi = (__nv_bfloat16*)(sm + SM_H1HI);
    __nv_bfloat16* sH1lo = (__nv_bfloat16*)(sm + SM_H1LO);
    __nv_bfloat16* sAhi  = (__nv_bfloat16*)(sm + SM_AHI);
    __nv_bfloat16* sAlo  = (__nv_bfloat16*)(sm + SM_ALO);
    float* sWT = sm + SM_WT;
    float* sEA = sm + SM_EA;
    float* sSH = sm + SM_SH;
    int*   sSD = (int*)(sm + SM_SD);

    const int tid  = threadIdx.x;
    const int wid  = tid >> 5;
    const int lane = tid & 31;

    for (int i = tid; i < 512; i += 512) sW1[i] = fw1[i];
    for (int i = tid; i < 2048; i += 512) {
        int n = i >> 5, kp = i & 31;
        float x0 = fw2[(2 * kp) * 64 + n] * 0.125f;
        float x1 = fw2[(2 * kp + 1) * 64 + n] * 0.125f;
        unsigned hi, lo;
        split2(x0, x1, hi, lo);
        *(unsigned*)(sW2hi + n * 72 + kp * 2) = hi;
        *(unsigned*)(sW2lo + n * 72 + kp * 2) = lo;
    }

    unsigned Bhi[2][4][2], Blo[2][4][2];
    {
        const float inv8 = 0.125f;
        const int n = wid * 16 + (lane >> 2);
#pragma unroll
        for (int nt = 0; nt < 2; nt++) {
#pragma unroll
            for (int kt = 0; kt < 4; kt++) {
                int k0 = kt * 16 + (lane & 3) * 2;
                int nn = n + nt * 8;
                float x0 = fw3[k0 * 256 + nn] * inv8;
                float x1 = fw3[(k0 + 1) * 256 + nn] * inv8;
                split2(x0, x1, Bhi[nt][kt][0], Blo[nt][kt][0]);
                float x2 = fw3[(k0 + 8) * 256 + nn] * inv8;
                float x3 = fw3[(k0 + 9) * 256 + nn] * inv8;
                split2(x2, x3, Bhi[nt][kt][1], Blo[nt][kt][1]);
            }
        }
    }
    const unsigned laneoff =
        ((lane & 7) + ((lane >> 3) & 1) * 8) * 144 + (lane >> 4) * 16;
    const unsigned h1hiU = smem_u32(sH1hi);
    const unsigned h1loU = smem_u32(sH1lo);
    const unsigned ahiU  = smem_u32(sAhi);
    const unsigned aloU  = smem_u32(sAlo);
    const unsigned w2hiU = smem_u32(sW2hi);
    const unsigned w2loU = smem_u32(sW2lo);
    __syncthreads();

    const float invs8 = 0.35355339059327373f;
    const float INV_SQRT3 = 0.5773502691896258f;

    for (int t = blockIdx.x; t < N_EDGES / 128; t += gridDim.x) {
        __syncthreads();
        const int e0 = t * 128;
        if (tid < 256) ((float4*)sEA)[tid] = ((const float4*)(ea + e0 * 8))[tid];
        if (tid < 128) ((float4*)sSH)[tid] = ((const float4*)(esh + e0 * 4))[tid];
        if (tid < 128) {
            int s = ei[e0 + tid];
            sSD[tid]       = s;
            sSD[128 + tid] = ei[N_EDGES + e0 + tid];
            atomicAdd(&g_deg[s], 1.0f);
        }
        __syncthreads();

        // ---- stage 1 -------------------------------------------------------
        {
            const int e = tid >> 2;
            const int q = tid & 3;
#pragma unroll
            for (int i = 0; i < 8; i++) {
                const int v0 = q * 16 + 2 * i;
                float a0 = 0.f, a1 = 0.f;
#pragma unroll
                for (int k = 0; k < 8; k++) {
                    float x = sEA[e * 8 + k];
                    a0 += x * sW1[k * 64 + v0];
                    a1 += x * sW1[k * 64 + v0 + 1];
                }
                a0 = silu(a0 * invs8);
                a1 = silu(a1 * invs8);
                unsigned hi, lo;
                split2(a0, a1, hi, lo);
                *(unsigned*)(sH1hi + e * 72 + v0) = hi;
                *(unsigned*)(sH1lo + e * 72 + v0) = lo;
            }
        }
        __syncthreads();

        // ---- stage 2 (mma bf16x3) ------------------------------------------
        {
            const int mtw = wid >> 1;
            const int ncb = (wid & 1) * 32;
            const int nb_l = ((lane >> 4) & 1) * 8 + (lane & 7);
            const int kb_l = ((lane >> 3) & 1) * 8;
            float C2[4][4];
#pragma unroll
            for (int nt = 0; nt < 4; nt++)
#pragma unroll
                for (int i = 0; i < 4; i++) C2[nt][i] = 0.f;
            const unsigned rowb = (unsigned)(mtw * 16 * 144) + laneoff;
#pragma unroll
            for (int kt = 0; kt < 4; kt++) {
                unsigned Ah[4], Al[4];
                ldsm4(Ah, h1hiU + rowb + kt * 32);
                ldsm4(Al, h1loU + rowb + kt * 32);
#pragma unroll
                for (int p = 0; p < 2; p++) {
                    unsigned off = (unsigned)((ncb + p * 16 + nb_l) * 144 +
                                              (kt * 16 + kb_l) * 2);
                    unsigned Bh[4], Bl[4];
                    ldsm4(Bh, w2hiU + off);
                    ldsm4(Bl, w2loU + off);
                    mma_bf16(C2[p * 2],     Ah, Bh);
                    mma_bf16(C2[p * 2],     Ah, Bl);
                    mma_bf16(C2[p * 2],     Al, Bh);
                    mma_bf16(C2[p * 2 + 1], Ah, Bh + 2);
                    mma_bf16(C2[p * 2 + 1], Ah, Bl + 2);
                    mma_bf16(C2[p * 2 + 1], Al, Bh + 2);
                }
            }
            const int r0 = mtw * 16 + (lane >> 2);
#pragma unroll
            for (int nt = 0; nt < 4; nt++) {
                int cc = ncb + nt * 8 + (lane & 3) * 2;
                float s0 = silu(C2[nt][0]), s1 = silu(C2[nt][1]);
                float s2 = silu(C2[nt][2]), s3 = silu(C2[nt][3]);
                unsigned h01, l01, h23, l23;
                split2(s0, s1, h01, l01);
                split2(s2, s3, h23, l23);
                *(unsigned*)(sAhi + r0 * 72 + cc) = h01;
                *(unsigned*)(sAlo + r0 * 72 + cc) = l01;
                *(unsigned*)(sAhi + (r0 + 8) * 72 + cc) = h23;
                *(unsigned*)(sAlo + (r0 + 8) * 72 + cc) = l23;
            }
        }
        __syncthreads();

        // ---- stage 3 + epilogue, two 64-edge halves ------------------------
#pragma unroll 1
        for (int half = 0; half < 2; half++) {
            const int ebh = half * 64;
            float C[4][2][4];
#pragma unroll
            for (int mt = 0; mt < 4; mt++)
#pragma unroll
                for (int nt = 0; nt < 2; nt++)
#pragma unroll
                    for (int i = 0; i < 4; i++) C[mt][nt][i] = 0.f;

#pragma unroll
            for (int mt = 0; mt < 4; mt++) {
                const unsigned rowb = (unsigned)((ebh + mt * 16) * 144) + laneoff;
#pragma unroll
                for (int kt = 0; kt < 4; kt++) {
                    unsigned Ah[4], Al[4];
                    ldsm4(Ah, ahiU + rowb + kt * 32);
                    ldsm4(Al, aloU + rowb + kt * 32);
#pragma unroll
                    for (int nt = 0; nt < 2; nt++) {
                        mma_bf16(C[mt][nt], Ah, Bhi[nt][kt]);
                        mma_bf16(C[mt][nt], Ah, Blo[nt][kt]);
                        mma_bf16(C[mt][nt], Al, Bhi[nt][kt]);
                    }
                }
            }
#pragma unroll
            for (int mt = 0; mt < 4; mt++) {
#pragma unroll
                for (int nt = 0; nt < 2; nt++) {
                    int r = mt * 16 + (lane >> 2);
                    int cc = wid * 16 + nt * 8 + (lane & 3) * 2;
                    *(float2*)(sWT + r * 264 + cc) = make_float2(C[mt][nt][0], C[mt][nt][1]);
                    *(float2*)(sWT + (r + 8) * 264 + cc) = make_float2(C[mt][nt][2], C[mt][nt][3]);
                }
            }
            __syncthreads();

#pragma unroll
            for (int j = 0; j < 2; j++) {
                const int s = tid + 512 * j;
                const int el = s >> 4, vq = s & 15;
                const int eg = ebh + el;
                const float4 wA = *(const float4*)(sWT + el * 264 + vq * 4);
                const float4 wB = *(const float4*)(sWT + el * 264 + 64 + vq * 4);
                const float4 wC = *(const float4*)(sWT + el * 264 + 128 + vq * 4);
                const float4 wD = *(const float4*)(sWT + el * 264 + 192 + vq * 4);
                const int src = sSD[eg], dstn = sSD[128 + eg];
                const float sh0 = sSH[eg * 4];
                const float s1x = sSH[eg * 4 + 1], s1y = sSH[eg * 4 + 2], s1z = sSH[eg * 4 + 3];

                const float4 es  = *(const float4*)(g_ys + dstn * 64 + vq * 4);
                const float4 ev0 = *(const float4*)(g_yv + dstn * 192 +       vq * 4);
                const float4 ev1 = *(const float4*)(g_yv + dstn * 192 +  64 + vq * 4);
                const float4 ev2 = *(const float4*)(g_yv + dstn * 192 + 128 + vq * 4);

                red4(g_ns + src * 128 + vq * 4,
                     wA.x * es.x * sh0, wA.y * es.y * sh0,
                     wA.z * es.z * sh0, wA.w * es.w * sh0);
                float4 dv;
                dv.x = ev0.x * s1x + ev1.x * s1y + ev2.x * s1z;
                dv.y = ev0.y * s1x + ev1.y * s1y + ev2.y * s1z;
                dv.z = ev0.z * s1x + ev1.z * s1y + ev2.z * s1z;
                dv.w = ev0.w * s1x + ev1.w * s1y + ev2.w * s1z;
                red4(g_ns + src * 128 + 64 + vq * 4,
                     wD.x * dv.x * INV_SQRT3, wD.y * dv.y * INV_SQRT3,
                     wD.z * dv.z * INV_SQRT3, wD.w * dv.w * INV_SQRT3);
                float4 be = make_float4(wB.x * es.x, wB.y * es.y, wB.z * es.z, wB.w * es.w);
                float* b = g_nv + src * 384 + vq * 4;
                red4(b,       be.x * s1x, be.y * s1x, be.z * s1x, be.w * s1x);
                red4(b + 128, be.x * s1y, be.y * s1y, be.z * s1y, be.w * s1y);
                red4(b + 256, be.x * s1z, be.y * s1z, be.z * s1z, be.w * s1z);
                float* b2 = g_nv + src * 384 + 64 + vq * 4;
                red4(b2,       wC.x * ev0.x * sh0, wC.y * ev0.y * sh0,
                               wC.z * ev0.z * sh0, wC.w * ev0.w * sh0);
                red4(b2 + 128, wC.x * ev1.x * sh0, wC.y * ev1.y * sh0,
                               wC.z * ev1.z * sh0, wC.w * ev1.w * sh0);
                red4(b2 + 256, wC.x * ev2.x * sh0, wC.y * ev2.y * sh0,
                               wC.z * ev2.z * sh0, wC.w * ev2.w * sh0);
            }
            __syncthreads();
        }
    }
}

// ---------------- K3: output GEMM (mma bf16x3) + residual + RMS norm --------
// Tile = 32 nodes. A = [ns(32); nv_x(32); nv_y(32); nv_z(32)] = 128 x K128.
// Warp w owns m-tile w (w<2 -> w2s, else w2v). inv2 folded into B (fp32).
// C spilled to smem; phase 2 = residual + RMS (former K3 epilogue).
#define K3_AHI  0        // 8704  (128 x 136 bf16)
#define K3_ALO  8704
#define K3_BSHI 17408    // 4352  (64 x 136 bf16)
#define K3_BSLO 21760
#define K3_BVHI 26112
#define K3_BVLO 30464
#define K3_SP   34816    // 8704  (128 x 68 f32)
#define K3_SMEM (43520 * 4)
__global__ __launch_bounds__(256, 1) void k_node_out(
    const float* __restrict__ w2s, const float* __restrict__ w2v,
    const float* __restrict__ gs, const float* __restrict__ gv,
    float* __restrict__ out)
{
    extern __shared__ float sm[];
    __nv_bfloat16* sAhi = (__nv_bfloat16*)(sm + K3_AHI);
    __nv_bfloat16* sAlo = (__nv_bfloat16*)(sm + K3_ALO);
    __nv_bfloat16* sBShi = (__nv_bfloat16*)(sm + K3_BSHI);
    __nv_bfloat16* sBSlo = (__nv_bfloat16*)(sm + K3_BSLO);
    __nv_bfloat16* sBVhi = (__nv_bfloat16*)(sm + K3_BVHI);
    __nv_bfloat16* sBVlo = (__nv_bfloat16*)(sm + K3_BVLO);
    float* sSP = sm + K3_SP;

    const int tid  = threadIdx.x;
    const int wid  = tid >> 5;
    const int lane = tid & 31;
    const float inv2 = 0.08838834764831845f;   // 1/sqrt(128), folded into B

    // one-time: B tiles (w2^T, bf16 hi/lo, inv2 folded in fp32)
    for (int i = tid; i < 4096; i += 256) {
        int n = i >> 6, up = i & 63;
        float x0 = w2s[(2 * up) * 64 + n] * inv2;
        float x1 = w2s[(2 * up + 1) * 64 + n] * inv2;
        unsigned hi, lo;
        split2(x0, x1, hi, lo);
        *(unsigned*)(sBShi + n * 136 + up * 2) = hi;
        *(unsigned*)(sBSlo + n * 136 + up * 2) = lo;
        x0 = w2v[(2 * up) * 64 + n] * inv2;
        x1 = w2v[(2 * up + 1) * 64 + n] * inv2;
        split2(x0, x1, hi, lo);
        *(unsigned*)(sBVhi + n * 136 + up * 2) = hi;
        *(unsigned*)(sBVlo + n * 136 + up * 2) = lo;
    }

    const unsigned laneoffA =
        ((lane & 7) + ((lane >> 3) & 1) * 8) * 272 + (lane >> 4) * 16;
    const int nb_l = ((lane >> 4) & 1) * 8 + (lane & 7);
    const int kb_l = ((lane >> 3) & 1) * 8;
    const unsigned ahiU = smem_u32(sAhi);
    const unsigned aloU = smem_u32(sAlo);
    const unsigned bhiU = smem_u32((wid < 2) ? sBShi : sBVhi);
    const unsigned bloU = smem_u32((wid < 2) ? sBSlo : sBVlo);

    for (int t = blockIdx.x; t < N_NODES / 32; t += gridDim.x) {
        __syncthreads();
        const int n0 = t * 32;

        // fill A tiles: row r<32: ns[n0+r]; else nv[n0+(r-32)&31][(r-32)>>5]
        {
            const int r = tid >> 1;
            const int hh = tid & 1;
            const float* src;
            if (r < 32) src = g_ns + (n0 + r) * 128;
            else src = g_nv + (n0 + ((r - 32) & 31)) * 384 + ((r - 32) >> 5) * 128;
#pragma unroll
            for (int c = 0; c < 32; c++) {
                int u2 = hh * 32 + c;
                float2 x = *(const float2*)(src + u2 * 2);
                unsigned hi, lo;
                split2(x.x, x.y, hi, lo);
                *(unsigned*)(sAhi + r * 136 + u2 * 2) = hi;
                *(unsigned*)(sAlo + r * 136 + u2 * 2) = lo;
            }
        }
        __syncthreads();

        // GEMM: warp = m-tile wid; N=64; K=128
        {
            float C[8][4];
#pragma unroll
            for (int nt = 0; nt < 8; nt++)
#pragma unroll
                for (int i = 0; i < 4; i++) C[nt][i] = 0.f;
            const unsigned rowb = (unsigned)(wid * 16 * 272) + laneoffA;
#pragma unroll
            for (int kt = 0; kt < 8; kt++) {
                unsigned Ah[4], Al[4];
                ldsm4(Ah, ahiU + rowb + kt * 32);
                ldsm4(Al, aloU + rowb + kt * 32);
#pragma unroll
                for (int p = 0; p < 4; p++) {
                    unsigned off = (unsigned)((p * 16 + nb_l) * 272 +
                                              (kt * 16 + kb_l) * 2);
                    unsigned Bh[4], Bl[4];
                    ldsm4(Bh, bhiU + off);
                    ldsm4(Bl, bloU + off);
                    mma_bf16(C[p * 2],     Ah, Bh);
                    mma_bf16(C[p * 2],     Ah, Bl);
                    mma_bf16(C[p * 2],     Al, Bh);
                    mma_bf16(C[p * 2 + 1], Ah, Bh + 2);
                    mma_bf16(C[p * 2 + 1], Ah, Bl + 2);
                    mma_bf16(C[p * 2 + 1], Al, Bh + 2);
                }
            }
            const int r0 = wid * 16 + (lane >> 2);
#pragma unroll
            for (int nt = 0; nt < 8; nt++) {
                int cc = nt * 8 + (lane & 3) * 2;
                *(float2*)(sSP + r0 * 68 + cc) = make_float2(C[nt][0], C[nt][1]);
                *(float2*)(sSP + (r0 + 8) * 68 + cc) = make_float2(C[nt][2], C[nt][3]);
            }
        }
        __syncthreads();

        // phase 2: residual + RMS + write (warp = 4 nodes, lane = col pair)
        {
            const int vt = lane;
#pragma unroll
            for (int k = 0; k < 4; k++) {
                const int nl = wid * 4 + k;
                const int n = n0 + nl;
                const float dn = rsqrtf(fmaxf(g_deg[n], 1.0f));
                float2 o = *(const float2*)(sSP + nl * 68 + vt * 2);
                float2 scs = *(const float2*)(g_scs + n * 64 + vt * 2);
                float s0 = o.x * dn + scs.x;
                float s1 = o.y * dn + scs.y;
                float v0[3], v1[3];
                float vsum = 0.f;
#pragma unroll
                for (int d = 0; d < 3; d++) {
                    float2 q = *(const float2*)(sSP + (32 + d * 32 + nl) * 68 + vt * 2);
                    float2 scv = *(const float2*)(g_scv + n * 192 + d * 64 + vt * 2);
                    float a = q.x * dn + scv.x;
                    float b = q.y * dn + scv.y;
                    v0[d] = a; v1[d] = b;
                    vsum += a * a + b * b;
                }
                float ssum = s0 * s0 + s1 * s1;
#pragma unroll
                for (int off = 16; off; off >>= 1) {
                    ssum += __shfl_xor_sync(0xffffffffu, ssum, off);
                    vsum += __shfl_xor_sync(0xffffffffu, vsum, off);
                }
                const float rs = rsqrtf(ssum * (1.0f / 64.0f)  + 1e-5f);
                const float rv = rsqrtf(vsum * (1.0f / 192.0f) + 1e-5f);
                *(float2*)(out + n * 256 + vt * 2) =
                    make_float2(s0 * rs * gs[vt * 2], s1 * rs * gs[vt * 2 + 1]);
                const float gv0 = gv[vt * 2] * rv, gv1 = gv[vt * 2 + 1] * rv;
#pragma unroll
                for (int d = 0; d < 3; d++) {
                    out[n * 256 + 64 + (vt * 2)     * 3 + d] = v0[d] * gv0;
                    out[n * 256 + 64 + (vt * 2 + 1) * 3 + d] = v1[d] * gv1;
                }
            }
        }
    }
}

// ---------------- launcher ----------------------------------------------------
extern "C" void kernel_launch(void* const* d_in, const int* in_sizes, int n_in,
                              void* d_out, int out_size)
{
    const float* nh   = (const float*)d_in[0];
    const float* ea   = (const float*)d_in[1];
    const float* esh  = (const float*)d_in[2];
    const float* w1s  = (const float*)d_in[3];
    const float* w1v  = (const float*)d_in[4];
    const float* wscs = (const float*)d_in[5];
    const float* wscv = (const float*)d_in[6];
    const float* w2s  = (const float*)d_in[7];
    const float* w2v  = (const float*)d_in[8];
    const float* fw1  = (const float*)d_in[9];
    const float* fw2  = (const float*)d_in[10];
    const float* fw3  = (const float*)d_in[11];
    const float* gs   = (const float*)d_in[12];
    const float* gv   = (const float*)d_in[13];
    const int*   eidx = (const int*)d_in[14];
    float* out = (float*)d_out;

    cudaFuncSetAttribute(k_node_in,  cudaFuncAttributeMaxDynamicSharedMemorySize, K1_SMEM);
    cudaFuncSetAttribute(k_edge,     cudaFuncAttributeMaxDynamicSharedMemorySize, K2_SMEM);
    cudaFuncSetAttribute(k_node_out, cudaFuncAttributeMaxDynamicSharedMemorySize, K3_SMEM);

    k_node_in<<<296, 256, K1_SMEM>>>(nh, w1s, w1v, wscs, wscv);
    k_edge<<<148, 512, K2_SMEM>>>(ea, esh, eidx, fw1, fw2, fw3);
    k_node_out<<<148, 256, K3_SMEM>>>(w2s, w2v, gs, gv, out);
}

// round 13
// speedup vs baseline: 1.0248x; 1.0248x over previous
#include <cuda_runtime.h>
#include <cuda_bf16.h>
#include <math.h>

#define N_NODES 20000
#define N_EDGES 320000

// ---------------- scratch (device globals) ----------------------------------
__device__ __align__(16) float g_ys [N_NODES * 64];
__device__ __align__(16) float g_yv [N_NODES * 192];
__device__ __align__(16) float g_scs[N_NODES * 64];
__device__ __align__(16) float g_scv[N_NODES * 192];
__device__ __align__(16) float g_ns [N_NODES * 128];
__device__ __align__(16) float g_nv [N_NODES * 384];
__device__ __align__(16) float g_deg[N_NODES];

typedef unsigned long long ull;

// ---------------- helpers ----------------------------------------------------
__device__ __forceinline__ void red4(float* p, float x, float y, float z, float w) {
    asm volatile("red.global.add.v4.f32 [%0], {%1,%2,%3,%4};"
                 :: "l"(p), "f"(x), "f"(y), "f"(z), "f"(w) : "memory");
}
__device__ __forceinline__ float silu(float x) {
    return x * (1.0f / (1.0f + __expf(-x)));
}
__device__ __forceinline__ ull ffma2(ull a, ull b, ull c) {
    ull d;
    asm("fma.rn.f32x2 %0, %1, %2, %3;" : "=l"(d) : "l"(a), "l"(b), "l"(c));
    return d;
}
__device__ __forceinline__ ull bcast2(float x) {
    ull r;
    asm("mov.b64 %0, {%1, %1};" : "=l"(r) : "f"(x));
    return r;
}
__device__ __forceinline__ void unpack2(ull p, float& x, float& y) {
    asm("mov.b64 {%0, %1}, %2;" : "=f"(x), "=f"(y) : "l"(p));
}
__device__ __forceinline__ unsigned smem_u32(const void* p) {
    unsigned a;
    asm("{ .reg .u64 t; cvta.to.shared.u64 t, %1; cvt.u32.u64 %0, t; }"
        : "=r"(a) : "l"(p));
    return a;
}
__device__ __forceinline__ void split2(float a, float b, unsigned& hi, unsigned& lo) {
    __nv_bfloat162 H, L;
    H.x = __float2bfloat16(a);
    H.y = __float2bfloat16(b);
    L.x = __float2bfloat16(a - __bfloat162float(H.x));
    L.y = __float2bfloat16(b - __bfloat162float(H.y));
    hi = *(unsigned*)&H;
    lo = *(unsigned*)&L;
}
__device__ __forceinline__ void mma_bf16(float* c, const unsigned* a, const unsigned* b) {
    asm volatile(
        "mma.sync.aligned.m16n8k16.row.col.f32.bf16.bf16.f32 "
        "{%0,%1,%2,%3}, {%4,%5,%6,%7}, {%8,%9}, {%0,%1,%2,%3};"
        : "+f"(c[0]), "+f"(c[1]), "+f"(c[2]), "+f"(c[3])
        : "r"(a[0]), "r"(a[1]), "r"(a[2]), "r"(a[3]), "r"(b[0]), "r"(b[1]));
}
__device__ __forceinline__ void ldsm4(unsigned* r, unsigned addr) {
    asm volatile("ldmatrix.sync.aligned.m8n8.x4.shared.b16 {%0,%1,%2,%3}, [%4];"
                 : "=r"(r[0]), "=r"(r[1]), "=r"(r[2]), "=r"(r[3]) : "r"(addr));
}

// ---------------- K1: zero scratch + node input transforms (mma bf16x3) -----
#define K1_SX   0
#define K1_AHI  8224
#define K1_ALO  12832
#define K1_SMEM (17440 * 4)
__global__ __launch_bounds__(256, 2) void k_node_in(
    const float* __restrict__ nh,
    const float* __restrict__ w1s, const float* __restrict__ w1v,
    const float* __restrict__ wscs, const float* __restrict__ wscv)
{
    extern __shared__ float sm[];
    float* sX = sm + K1_SX;                              // [32][257]
    __nv_bfloat16* sAhi = (__nv_bfloat16*)(sm + K1_AHI); // [128][72]
    __nv_bfloat16* sAlo = (__nv_bfloat16*)(sm + K1_ALO);

    const int tid  = threadIdx.x;
    const int wid  = tid >> 5;
    const int lane = tid & 31;

    {
        int gi = blockIdx.x * blockDim.x + tid;
        int gstr = gridDim.x * blockDim.x;
        float4 z = make_float4(0.f, 0.f, 0.f, 0.f);
        for (int j = gi; j < N_NODES * 128 / 4; j += gstr) ((float4*)g_ns)[j] = z;
        for (int j = gi; j < N_NODES * 384 / 4; j += gstr) ((float4*)g_nv)[j] = z;
        for (int j = gi; j < N_NODES; j += gstr) g_deg[j] = 0.f;
    }

    unsigned BH[2][4][2][2], BL[2][4][2][2];
    {
        const float inv = 0.125f;
        const float* srcS = (wid < 4) ? w1s : wscs;
        const float* srcV = (wid < 4) ? w1v : wscv;
        const int nc = (wid & 3) * 16 + (lane >> 2);
#pragma unroll
        for (int sv = 0; sv < 2; sv++) {
            const float* src = sv ? srcV : srcS;
#pragma unroll
            for (int nt = 0; nt < 2; nt++) {
#pragma unroll
                for (int kt = 0; kt < 4; kt++) {
                    int k0 = kt * 16 + (lane & 3) * 2;
                    int nn = nc + nt * 8;
                    float x0 = src[k0 * 64 + nn] * inv;
                    float x1 = src[(k0 + 1) * 64 + nn] * inv;
                    split2(x0, x1, BH[sv][kt][nt][0], BL[sv][kt][nt][0]);
                    float x2 = src[(k0 + 8) * 64 + nn] * inv;
                    float x3 = src[(k0 + 9) * 64 + nn] * inv;
                    split2(x2, x3, BH[sv][kt][nt][1], BL[sv][kt][nt][1]);
                }
            }
        }
    }
    const unsigned laneoff =
        ((lane & 7) + ((lane >> 3) & 1) * 8) * 144 + (lane >> 4) * 16;
    const unsigned ahiU = smem_u32(sAhi);
    const unsigned aloU = smem_u32(sAlo);

    for (int t = blockIdx.x; t < N_NODES / 32; t += gridDim.x) {
        __syncthreads();
        const int n0 = t * 32;
        for (int i = tid; i < 32 * 256; i += 256) {
            int n = i >> 8, c = i & 255;
            sX[n * 257 + c] = nh[(n0 + n) * 256 + c];
        }
        __syncthreads();

        {
            const int r = tid >> 1;
            const int b = r >> 5;
            const float* base = sX + (r & 31) * 257;
            const int ch = (tid & 1) * 16;
#pragma unroll
            for (int c = 0; c < 16; c++) {
                int cp = ch + c;
                float x0, x1;
                if (b == 0) {
                    x0 = base[2 * cp];
                    x1 = base[2 * cp + 1];
                } else {
                    x0 = base[64 + (2 * cp) * 3 + (b - 1)];
                    x1 = base[64 + (2 * cp + 1) * 3 + (b - 1)];
                }
                unsigned hi, lo;
                split2(x0, x1, hi, lo);
                *(unsigned*)(sAhi + r * 72 + cp * 2) = hi;
                *(unsigned*)(sAlo + r * 72 + cp * 2) = lo;
            }
        }
        __syncthreads();

#pragma unroll
        for (int mt = 0; mt < 8; mt++) {
            const int sv = (mt < 2) ? 0 : 1;
            const unsigned rowb = (unsigned)(mt * 16 * 144) + laneoff;
            float C[2][4];
#pragma unroll
            for (int nt = 0; nt < 2; nt++)
#pragma unroll
                for (int i = 0; i < 4; i++) C[nt][i] = 0.f;
#pragma unroll
            for (int kt = 0; kt < 4; kt++) {
                unsigned Ah[4], Al[4];
                ldsm4(Ah, ahiU + rowb + kt * 32);
                ldsm4(Al, aloU + rowb + kt * 32);
#pragma unroll
                for (int nt = 0; nt < 2; nt++) {
                    mma_bf16(C[nt], Ah, BH[sv][kt][nt]);
                    mma_bf16(C[nt], Ah, BL[sv][kt][nt]);
                    mma_bf16(C[nt], Al, BH[sv][kt][nt]);
                }
            }
            const int b2 = mt >> 1;
            const int nA = n0 + (mt & 1) * 16 + (lane >> 2);
            const int nB = nA + 8;
#pragma unroll
            for (int nt = 0; nt < 2; nt++) {
                const int v = (wid & 3) * 16 + nt * 8 + (lane & 3) * 2;
                float* dstA;
                float* dstB;
                if (wid < 4) {
                    if (b2 == 0) { dstA = g_ys + nA * 64 + v; dstB = g_ys + nB * 64 + v; }
                    else {
                        dstA = g_yv + nA * 192 + (b2 - 1) * 64 + v;
                        dstB = g_yv + nB * 192 + (b2 - 1) * 64 + v;
                    }
                } else {
                    if (b2 == 0) { dstA = g_scs + nA * 64 + v; dstB = g_scs + nB * 64 + v; }
                    else {
                        dstA = g_scv + nA * 192 + (b2 - 1) * 64 + v;
                        dstB = g_scv + nB * 192 + (b2 - 1) * 64 + v;
                    }
                }
                *(float2*)dstA = make_float2(C[nt][0], C[nt][1]);
                *(float2*)dstB = make_float2(C[nt][2], C[nt][3]);
            }
        }
    }
}

// ---------------- K2: edge MLP (stages 2+3 on mma.sync) + TP + scatter ------
// Gathers for each half are prefetched into registers BEFORE the mma mainloop
// so the red4 memory-clobber chain never exposes their latency.
#define SM_W1   0        // 512
#define SM_W2HI 512      // 2304 (W2^T bf16 hi, [64 n][72 k])
#define SM_W2LO 2816     // 2304
#define SM_H1HI 5120     // 4608 ([128 e][72] bf16)
#define SM_H1LO 9728     // 4608
#define SM_AHI  14336    // 4608 (h2 tiles)
#define SM_ALO  18944    // 4608
#define SM_WT   23552    // 64*264 = 16896
#define SM_EA   40448    // 1024
#define SM_SH   41472    // 512
#define SM_SD   41984    // 256 ints
#define K2_SMEM (42240 * 4)

__global__ __launch_bounds__(512, 1) void k_edge(
    const float* __restrict__ ea, const float* __restrict__ esh,
    const int* __restrict__ ei,
    const float* __restrict__ fw1, const float* __restrict__ fw2,
    const float* __restrict__ fw3)
{
    extern __shared__ float sm[];
    float* sW1 = sm + SM_W1;
    __nv_bfloat16* sW2hi = (__nv_bfloat16*)(sm + SM_W2HI);
    __nv_bfloat16* sW2lo = (__nv_bfloat16*)(sm + SM_W2LO);
    __nv_bfloat16* sH1hi = (__nv_bfloat16*)(sm + SM_H1HI);
    __nv_bfloat16* sH1lo = (__nv_bfloat16*)(sm + SM_H1LO);
    __nv_bfloat16* sAhi  = (__nv_bfloat16*)(sm + SM_AHI);
    __nv_bfloat16* sAlo  = (__nv_bfloat16*)(sm + SM_ALO);
    float* sWT = sm + SM_WT;
    float* sEA = sm + SM_EA;
    float* sSH = sm + SM_SH;
    int*   sSD = (int*)(sm + SM_SD);

    const int tid  = threadIdx.x;
    const int wid  = tid >> 5;
    const int lane = tid & 31;

    for (int i = tid; i < 512; i += 512) sW1[i] = fw1[i];
    for (int i = tid; i < 2048; i += 512) {
        int n = i >> 5, kp = i & 31;
        float x0 = fw2[(2 * kp) * 64 + n] * 0.125f;
        float x1 = fw2[(2 * kp + 1) * 64 + n] * 0.125f;
        unsigned hi, lo;
        split2(x0, x1, hi, lo);
        *(unsigned*)(sW2hi + n * 72 + kp * 2) = hi;
        *(unsigned*)(sW2lo + n * 72 + kp * 2) = lo;
    }

    unsigned Bhi[2][4][2], Blo[2][4][2];
    {
        const float inv8 = 0.125f;
        const int n = wid * 16 + (lane >> 2);
#pragma unroll
        for (int nt = 0; nt < 2; nt++) {
#pragma unroll
            for (int kt = 0; kt < 4; kt++) {
                int k0 = kt * 16 + (lane & 3) * 2;
                int nn = n + nt * 8;
                float x0 = fw3[k0 * 256 + nn] * inv8;
                float x1 = fw3[(k0 + 1) * 256 + nn] * inv8;
                split2(x0, x1, Bhi[nt][kt][0], Blo[nt][kt][0]);
                float x2 = fw3[(k0 + 8) * 256 + nn] * inv8;
                float x3 = fw3[(k0 + 9) * 256 + nn] * inv8;
                split2(x2, x3, Bhi[nt][kt][1], Blo[nt][kt][1]);
            }
        }
    }
    const unsigned laneoff =
        ((lane & 7) + ((lane >> 3) & 1) * 8) * 144 + (lane >> 4) * 16;
    const unsigned h1hiU = smem_u32(sH1hi);
    const unsigned h1loU = smem_u32(sH1lo);
    const unsigned ahiU  = smem_u32(sAhi);
    const unsigned aloU  = smem_u32(sAlo);
    const unsigned w2hiU = smem_u32(sW2hi);
    const unsigned w2loU = smem_u32(sW2lo);
    __syncthreads();

    const float invs8 = 0.35355339059327373f;
    const float INV_SQRT3 = 0.5773502691896258f;

    for (int t = blockIdx.x; t < N_EDGES / 128; t += gridDim.x) {
        __syncthreads();
        const int e0 = t * 128;
        if (tid < 256) ((float4*)sEA)[tid] = ((const float4*)(ea + e0 * 8))[tid];
        if (tid < 128) ((float4*)sSH)[tid] = ((const float4*)(esh + e0 * 4))[tid];
        if (tid < 128) {
            int s = ei[e0 + tid];
            sSD[tid]       = s;
            sSD[128 + tid] = ei[N_EDGES + e0 + tid];
            atomicAdd(&g_deg[s], 1.0f);
        }
        __syncthreads();

        // ---- stage 1 -------------------------------------------------------
        {
            const int e = tid >> 2;
            const int q = tid & 3;
#pragma unroll
            for (int i = 0; i < 8; i++) {
                const int v0 = q * 16 + 2 * i;
                float a0 = 0.f, a1 = 0.f;
#pragma unroll
                for (int k = 0; k < 8; k++) {
                    float x = sEA[e * 8 + k];
                    a0 += x * sW1[k * 64 + v0];
                    a1 += x * sW1[k * 64 + v0 + 1];
                }
                a0 = silu(a0 * invs8);
                a1 = silu(a1 * invs8);
                unsigned hi, lo;
                split2(a0, a1, hi, lo);
                *(unsigned*)(sH1hi + e * 72 + v0) = hi;
                *(unsigned*)(sH1lo + e * 72 + v0) = lo;
            }
        }
        __syncthreads();

        // ---- stage 2 (mma bf16x3) ------------------------------------------
        {
            const int mtw = wid >> 1;
            const int ncb = (wid & 1) * 32;
            const int nb_l = ((lane >> 4) & 1) * 8 + (lane & 7);
            const int kb_l = ((lane >> 3) & 1) * 8;
            float C2[4][4];
#pragma unroll
            for (int nt = 0; nt < 4; nt++)
#pragma unroll
                for (int i = 0; i < 4; i++) C2[nt][i] = 0.f;
            const unsigned rowb = (unsigned)(mtw * 16 * 144) + laneoff;
#pragma unroll
            for (int kt = 0; kt < 4; kt++) {
                unsigned Ah[4], Al[4];
                ldsm4(Ah, h1hiU + rowb + kt * 32);
                ldsm4(Al, h1loU + rowb + kt * 32);
#pragma unroll
                for (int p = 0; p < 2; p++) {
                    unsigned off = (unsigned)((ncb + p * 16 + nb_l) * 144 +
                                              (kt * 16 + kb_l) * 2);
                    unsigned Bh[4], Bl[4];
                    ldsm4(Bh, w2hiU + off);
                    ldsm4(Bl, w2loU + off);
                    mma_bf16(C2[p * 2],     Ah, Bh);
                    mma_bf16(C2[p * 2],     Ah, Bl);
                    mma_bf16(C2[p * 2],     Al, Bh);
                    mma_bf16(C2[p * 2 + 1], Ah, Bh + 2);
                    mma_bf16(C2[p * 2 + 1], Ah, Bl + 2);
                    mma_bf16(C2[p * 2 + 1], Al, Bh + 2);
                }
            }
            const int r0 = mtw * 16 + (lane >> 2);
#pragma unroll
            for (int nt = 0; nt < 4; nt++) {
                int cc = ncb + nt * 8 + (lane & 3) * 2;
                float s0 = silu(C2[nt][0]), s1 = silu(C2[nt][1]);
                float s2 = silu(C2[nt][2]), s3 = silu(C2[nt][3]);
                unsigned h01, l01, h23, l23;
                split2(s0, s1, h01, l01);
                split2(s2, s3, h23, l23);
                *(unsigned*)(sAhi + r0 * 72 + cc) = h01;
                *(unsigned*)(sAlo + r0 * 72 + cc) = l01;
                *(unsigned*)(sAhi + (r0 + 8) * 72 + cc) = h23;
                *(unsigned*)(sAlo + (r0 + 8) * 72 + cc) = l23;
            }
        }
        __syncthreads();

        // ---- stage 3 + epilogue, two 64-edge halves ------------------------
#pragma unroll 1
        for (int half = 0; half < 2; half++) {
            const int ebh = half * 64;

            // prefetch this half's TP gathers into registers (latency hidden
            // under the mma mainloop + spill below)
            float4 pes[2], pev[2][3];
#pragma unroll
            for (int j = 0; j < 2; j++) {
                const int s = tid + 512 * j;
                const int el = s >> 4, vq = s & 15;
                const int dstn = sSD[128 + ebh + el];
                pes[j]    = *(const float4*)(g_ys + dstn * 64 + vq * 4);
                pev[j][0] = *(const float4*)(g_yv + dstn * 192 +       vq * 4);
                pev[j][1] = *(const float4*)(g_yv + dstn * 192 +  64 + vq * 4);
                pev[j][2] = *(const float4*)(g_yv + dstn * 192 + 128 + vq * 4);
            }

            float C[4][2][4];
#pragma unroll
            for (int mt = 0; mt < 4; mt++)
#pragma unroll
                for (int nt = 0; nt < 2; nt++)
#pragma unroll
                    for (int i = 0; i < 4; i++) C[mt][nt][i] = 0.f;

#pragma unroll
            for (int mt = 0; mt < 4; mt++) {
                const unsigned rowb = (unsigned)((ebh + mt * 16) * 144) + laneoff;
#pragma unroll
                for (int kt = 0; kt < 4; kt++) {
                    unsigned Ah[4], Al[4];
                    ldsm4(Ah, ahiU + rowb + kt * 32);
                    ldsm4(Al, aloU + rowb + kt * 32);
#pragma unroll
                    for (int nt = 0; nt < 2; nt++) {
                        mma_bf16(C[mt][nt], Ah, Bhi[nt][kt]);
                        mma_bf16(C[mt][nt], Ah, Blo[nt][kt]);
                        mma_bf16(C[mt][nt], Al, Bhi[nt][kt]);
                    }
                }
            }
#pragma unroll
            for (int mt = 0; mt < 4; mt++) {
#pragma unroll
                for (int nt = 0; nt < 2; nt++) {
                    int r = mt * 16 + (lane >> 2);
                    int cc = wid * 16 + nt * 8 + (lane & 3) * 2;
                    *(float2*)(sWT + r * 264 + cc) = make_float2(C[mt][nt][0], C[mt][nt][1]);
                    *(float2*)(sWT + (r + 8) * 264 + cc) = make_float2(C[mt][nt][2], C[mt][nt][3]);
                }
            }
            __syncthreads();

#pragma unroll
            for (int j = 0; j < 2; j++) {
                const int s = tid + 512 * j;
                const int el = s >> 4, vq = s & 15;
                const int eg = ebh + el;
                const float4 wA = *(const float4*)(sWT + el * 264 + vq * 4);
                const float4 wB = *(const float4*)(sWT + el * 264 + 64 + vq * 4);
                const float4 wC = *(const float4*)(sWT + el * 264 + 128 + vq * 4);
                const float4 wD = *(const float4*)(sWT + el * 264 + 192 + vq * 4);
                const int src = sSD[eg];
                const float sh0 = sSH[eg * 4];
                const float s1x = sSH[eg * 4 + 1], s1y = sSH[eg * 4 + 2], s1z = sSH[eg * 4 + 3];

                const float4 es  = pes[j];
                const float4 ev0 = pev[j][0];
                const float4 ev1 = pev[j][1];
                const float4 ev2 = pev[j][2];

                red4(g_ns + src * 128 + vq * 4,
                     wA.x * es.x * sh0, wA.y * es.y * sh0,
                     wA.z * es.z * sh0, wA.w * es.w * sh0);
                float4 dv;
                dv.x = ev0.x * s1x + ev1.x * s1y + ev2.x * s1z;
                dv.y = ev0.y * s1x + ev1.y * s1y + ev2.y * s1z;
                dv.z = ev0.z * s1x + ev1.z * s1y + ev2.z * s1z;
                dv.w = ev0.w * s1x + ev1.w * s1y + ev2.w * s1z;
                red4(g_ns + src * 128 + 64 + vq * 4,
                     wD.x * dv.x * INV_SQRT3, wD.y * dv.y * INV_SQRT3,
                     wD.z * dv.z * INV_SQRT3, wD.w * dv.w * INV_SQRT3);
                float4 be = make_float4(wB.x * es.x, wB.y * es.y, wB.z * es.z, wB.w * es.w);
                float* b = g_nv + src * 384 + vq * 4;
                red4(b,       be.x * s1x, be.y * s1x, be.z * s1x, be.w * s1x);
                red4(b + 128, be.x * s1y, be.y * s1y, be.z * s1y, be.w * s1y);
                red4(b + 256, be.x * s1z, be.y * s1z, be.z * s1z, be.w * s1z);
                float* b2 = g_nv + src * 384 + 64 + vq * 4;
                red4(b2,       wC.x * ev0.x * sh0, wC.y * ev0.y * sh0,
                               wC.z * ev0.z * sh0, wC.w * ev0.w * sh0);
                red4(b2 + 128, wC.x * ev1.x * sh0, wC.y * ev1.y * sh0,
                               wC.z * ev1.z * sh0, wC.w * ev1.w * sh0);
                red4(b2 + 256, wC.x * ev2.x * sh0, wC.y * ev2.y * sh0,
                               wC.z * ev2.z * sh0, wC.w * ev2.w * sh0);
            }
            __syncthreads();
        }
    }
}

// ---------------- K3: output GEMM + residual + RMS norm (FFMA2, R11) --------
#define K3W 8576
#define K3_SMEM ((2 * K3W + 16 * 128 + 16 * 384) * 4)
__global__ __launch_bounds__(256, 2) void k_node_out(
    const float* __restrict__ w2s, const float* __restrict__ w2v,
    const float* __restrict__ gs, const float* __restrict__ gv,
    float* __restrict__ out)
{
    extern __shared__ float sm[];
    float* sWsT = sm;                 // [32][268]
    float* sWvT = sm + K3W;
    float* sNs  = sm + 2 * K3W;
    float* sNv  = sm + 2 * K3W + 2048;

    const int tid = threadIdx.x;
    for (int i = tid; i < 8192; i += 256) {
        int u = i >> 6, v = i & 63;
        sWsT[(v >> 1) * 268 + u * 2 + (v & 1)] = w2s[i];
        sWvT[(v >> 1) * 268 + u * 2 + (v & 1)] = w2v[i];
    }

    const int vt   = tid & 31;
    const int warp = tid >> 5;
    const float inv2 = 0.08838834764831845f;

    for (int t = blockIdx.x; t < N_NODES / 16; t += gridDim.x) {
        __syncthreads();
        const int n0 = t * 16;
        for (int i = tid; i < 512; i += 256)
            ((float4*)sNs)[i] = ((const float4*)g_ns)[n0 * 32 + i];
        for (int i = tid; i < 1536; i += 256)
            ((float4*)sNv)[i] = ((const float4*)g_nv)[n0 * 96 + i];
        __syncthreads();

        ull oS[2] = {0ull, 0ull};
        ull oV[2][3] = {{0ull,0ull,0ull},{0ull,0ull,0ull}};
        for (int u = 0; u < 128; u += 2) {
            ulonglong2 wsp = *(const ulonglong2*)(sWsT + vt * 268 + u * 2);
            ulonglong2 wvp = *(const ulonglong2*)(sWvT + vt * 268 + u * 2);
#pragma unroll
            for (int k = 0; k < 2; k++) {
                int n = warp * 2 + k;
                float2 xs2 = *(const float2*)(sNs + n * 128 + u);
                oS[k] = ffma2(bcast2(xs2.x), wsp.x, oS[k]);
                oS[k] = ffma2(bcast2(xs2.y), wsp.y, oS[k]);
#pragma unroll
                for (int d = 0; d < 3; d++) {
                    float2 xv2 = *(const float2*)(sNv + n * 384 + d * 128 + u);
                    oV[k][d] = ffma2(bcast2(xv2.x), wvp.x, oV[k][d]);
                    oV[k][d] = ffma2(bcast2(xv2.y), wvp.y, oV[k][d]);
                }
            }
        }

#pragma unroll
        for (int k = 0; k < 2; k++) {
            const int n = n0 + warp * 2 + k;
            const float dn = rsqrtf(fmaxf(g_deg[n], 1.0f)) * inv2;
            float s0, s1;
            unpack2(oS[k], s0, s1);
            float2 scs = *(const float2*)(g_scs + n * 64 + vt * 2);
            s0 = s0 * dn + scs.x;
            s1 = s1 * dn + scs.y;
            float v0[3], v1[3];
            float vsum = 0.f;
#pragma unroll
            for (int d = 0; d < 3; d++) {
                float a, b;
                unpack2(oV[k][d], a, b);
                float2 scv = *(const float2*)(g_scv + n * 192 + d * 64 + vt * 2);
                a = a * dn + scv.x;
                b = b * dn + scv.y;
                v0[d] = a; v1[d] = b;
                vsum += a * a + b * b;
            }
            float ssum = s0 * s0 + s1 * s1;
#pragma unroll
            for (int off = 16; off; off >>= 1) {
                ssum += __shfl_xor_sync(0xffffffffu, ssum, off);
                vsum += __shfl_xor_sync(0xffffffffu, vsum, off);
            }
            const float rs = rsqrtf(ssum * (1.0f / 64.0f)  + 1e-5f);
            const float rv = rsqrtf(vsum * (1.0f / 192.0f) + 1e-5f);
            *(float2*)(out + n * 256 + vt * 2) =
                make_float2(s0 * rs * gs[vt * 2], s1 * rs * gs[vt * 2 + 1]);
            const float gv0 = gv[vt * 2] * rv, gv1 = gv[vt * 2 + 1] * rv;
#pragma unroll
            for (int d = 0; d < 3; d++) {
                out[n * 256 + 64 + (vt * 2)     * 3 + d] = v0[d] * gv0;
                out[n * 256 + 64 + (vt * 2 + 1) * 3 + d] = v1[d] * gv1;
            }
        }
    }
}

// ---------------- launcher ----------------------------------------------------
extern "C" void kernel_launch(void* const* d_in, const int* in_sizes, int n_in,
                              void* d_out, int out_size)
{
    const float* nh   = (const float*)d_in[0];
    const float* ea   = (const float*)d_in[1];
    const float* esh  = (const float*)d_in[2];
    const float* w1s  = (const float*)d_in[3];
    const float* w1v  = (const float*)d_in[4];
    const float* wscs = (const float*)d_in[5];
    const float* wscv = (const float*)d_in[6];
    const float* w2s  = (const float*)d_in[7];
    const float* w2v  = (const float*)d_in[8];
    const float* fw1  = (const float*)d_in[9];
    const float* fw2  = (const float*)d_in[10];
    const float* fw3  = (const float*)d_in[11];
    const float* gs   = (const float*)d_in[12];
    const float* gv   = (const float*)d_in[13];
    const int*   eidx = (const int*)d_in[14];
    float* out = (float*)d_out;

    cudaFuncSetAttribute(k_node_in,  cudaFuncAttributeMaxDynamicSharedMemorySize, K1_SMEM);
    cudaFuncSetAttribute(k_edge,     cudaFuncAttributeMaxDynamicSharedMemorySize, K2_SMEM);
    cudaFuncSetAttribute(k_node_out, cudaFuncAttributeMaxDynamicSharedMemorySize, K3_SMEM);

    k_node_in<<<296, 256, K1_SMEM>>>(nh, w1s, w1v, wscs, wscv);
    k_edge<<<148, 512, K2_SMEM>>>(ea, esh, eidx, fw1, fw2, fw3);
    k_node_out<<<296, 256, K3_SMEM>>>(w2s, w2v, gs, gv, out);
}

// round 14
// speedup vs baseline: 1.0621x; 1.0364x over previous
#include <cuda_runtime.h>
#include <cuda_bf16.h>
#include <math.h>

#define N_NODES 20000
#define N_EDGES 320000

// ---------------- scratch (device globals) ----------------------------------
__device__ __align__(16) float g_ys [N_NODES * 64];
__device__ __align__(16) float g_yv [N_NODES * 192];
__device__ __align__(16) float g_scs[N_NODES * 64];
__device__ __align__(16) float g_scv[N_NODES * 192];
__device__ __align__(16) float g_ns [N_NODES * 128];
__device__ __align__(16) float g_nv [N_NODES * 384];
__device__ __align__(16) float g_deg[N_NODES];

typedef unsigned long long ull;

// ---------------- helpers ----------------------------------------------------
__device__ __forceinline__ void red4(float* p, float x, float y, float z, float w) {
    asm volatile("red.global.add.v4.f32 [%0], {%1,%2,%3,%4};"
                 :: "l"(p), "f"(x), "f"(y), "f"(z), "f"(w) : "memory");
}
__device__ __forceinline__ float silu(float x) {
    return x * (1.0f / (1.0f + __expf(-x)));
}
__device__ __forceinline__ ull ffma2(ull a, ull b, ull c) {
    ull d;
    asm("fma.rn.f32x2 %0, %1, %2, %3;" : "=l"(d) : "l"(a), "l"(b), "l"(c));
    return d;
}
__device__ __forceinline__ ull bcast2(float x) {
    ull r;
    asm("mov.b64 %0, {%1, %1};" : "=l"(r) : "f"(x));
    return r;
}
__device__ __forceinline__ void unpack2(ull p, float& x, float& y) {
    asm("mov.b64 {%0, %1}, %2;" : "=f"(x), "=f"(y) : "l"(p));
}
__device__ __forceinline__ unsigned smem_u32(const void* p) {
    unsigned a;
    asm("{ .reg .u64 t; cvta.to.shared.u64 t, %1; cvt.u32.u64 %0, t; }"
        : "=r"(a) : "l"(p));
    return a;
}
__device__ __forceinline__ void split2(float a, float b, unsigned& hi, unsigned& lo) {
    __nv_bfloat162 H, L;
    H.x = __float2bfloat16(a);
    H.y = __float2bfloat16(b);
    L.x = __float2bfloat16(a - __bfloat162float(H.x));
    L.y = __float2bfloat16(b - __bfloat162float(H.y));
    hi = *(unsigned*)&H;
    lo = *(unsigned*)&L;
}
__device__ __forceinline__ void mma_bf16(float* c, const unsigned* a, const unsigned* b) {
    asm volatile(
        "mma.sync.aligned.m16n8k16.row.col.f32.bf16.bf16.f32 "
        "{%0,%1,%2,%3}, {%4,%5,%6,%7}, {%8,%9}, {%0,%1,%2,%3};"
        : "+f"(c[0]), "+f"(c[1]), "+f"(c[2]), "+f"(c[3])
        : "r"(a[0]), "r"(a[1]), "r"(a[2]), "r"(a[3]), "r"(b[0]), "r"(b[1]));
}
__device__ __forceinline__ void ldsm4(unsigned* r, unsigned addr) {
    asm volatile("ldmatrix.sync.aligned.m8n8.x4.shared.b16 {%0,%1,%2,%3}, [%4];"
                 : "=r"(r[0]), "=r"(r[1]), "=r"(r[2]), "=r"(r[3]) : "r"(addr));
}

// ---------------- K1: zero scratch + node input transforms (mma bf16x3) -----
#define K1_SX   0
#define K1_AHI  8224
#define K1_ALO  12832
#define K1_SMEM (17440 * 4)
__global__ __launch_bounds__(256, 2) void k_node_in(
    const float* __restrict__ nh,
    const float* __restrict__ w1s, const float* __restrict__ w1v,
    const float* __restrict__ wscs, const float* __restrict__ wscv)
{
    extern __shared__ float sm[];
    float* sX = sm + K1_SX;                              // [32][257]
    __nv_bfloat16* sAhi = (__nv_bfloat16*)(sm + K1_AHI); // [128][72]
    __nv_bfloat16* sAlo = (__nv_bfloat16*)(sm + K1_ALO);

    const int tid  = threadIdx.x;
    const int wid  = tid >> 5;
    const int lane = tid & 31;

    {
        int gi = blockIdx.x * blockDim.x + tid;
        int gstr = gridDim.x * blockDim.x;
        float4 z = make_float4(0.f, 0.f, 0.f, 0.f);
        for (int j = gi; j < N_NODES * 128 / 4; j += gstr) ((float4*)g_ns)[j] = z;
        for (int j = gi; j < N_NODES * 384 / 4; j += gstr) ((float4*)g_nv)[j] = z;
        for (int j = gi; j < N_NODES; j += gstr) g_deg[j] = 0.f;
    }

    unsigned BH[2][4][2][2], BL[2][4][2][2];
    {
        const float inv = 0.125f;
        const float* srcS = (wid < 4) ? w1s : wscs;
        const float* srcV = (wid < 4) ? w1v : wscv;
        const int nc = (wid & 3) * 16 + (lane >> 2);
#pragma unroll
        for (int sv = 0; sv < 2; sv++) {
            const float* src = sv ? srcV : srcS;
#pragma unroll
            for (int nt = 0; nt < 2; nt++) {
#pragma unroll
                for (int kt = 0; kt < 4; kt++) {
                    int k0 = kt * 16 + (lane & 3) * 2;
                    int nn = nc + nt * 8;
                    float x0 = src[k0 * 64 + nn] * inv;
                    float x1 = src[(k0 + 1) * 64 + nn] * inv;
                    split2(x0, x1, BH[sv][kt][nt][0], BL[sv][kt][nt][0]);
                    float x2 = src[(k0 + 8) * 64 + nn] * inv;
                    float x3 = src[(k0 + 9) * 64 + nn] * inv;
                    split2(x2, x3, BH[sv][kt][nt][1], BL[sv][kt][nt][1]);
                }
            }
        }
    }
    const unsigned laneoff =
        ((lane & 7) + ((lane >> 3) & 1) * 8) * 144 + (lane >> 4) * 16;
    const unsigned ahiU = smem_u32(sAhi);
    const unsigned aloU = smem_u32(sAlo);

    for (int t = blockIdx.x; t < N_NODES / 32; t += gridDim.x) {
        __syncthreads();
        const int n0 = t * 32;
        for (int i = tid; i < 32 * 256; i += 256) {
            int n = i >> 8, c = i & 255;
            sX[n * 257 + c] = nh[(n0 + n) * 256 + c];
        }
        __syncthreads();

        {
            const int r = tid >> 1;
            const int b = r >> 5;
            const float* base = sX + (r & 31) * 257;
            const int ch = (tid & 1) * 16;
#pragma unroll
            for (int c = 0; c < 16; c++) {
                int cp = ch + c;
                float x0, x1;
                if (b == 0) {
                    x0 = base[2 * cp];
                    x1 = base[2 * cp + 1];
                } else {
                    x0 = base[64 + (2 * cp) * 3 + (b - 1)];
                    x1 = base[64 + (2 * cp + 1) * 3 + (b - 1)];
                }
                unsigned hi, lo;
                split2(x0, x1, hi, lo);
                *(unsigned*)(sAhi + r * 72 + cp * 2) = hi;
                *(unsigned*)(sAlo + r * 72 + cp * 2) = lo;
            }
        }
        __syncthreads();

#pragma unroll
        for (int mt = 0; mt < 8; mt++) {
            const int sv = (mt < 2) ? 0 : 1;
            const unsigned rowb = (unsigned)(mt * 16 * 144) + laneoff;
            float C[2][4];
#pragma unroll
            for (int nt = 0; nt < 2; nt++)
#pragma unroll
                for (int i = 0; i < 4; i++) C[nt][i] = 0.f;
#pragma unroll
            for (int kt = 0; kt < 4; kt++) {
                unsigned Ah[4], Al[4];
                ldsm4(Ah, ahiU + rowb + kt * 32);
                ldsm4(Al, aloU + rowb + kt * 32);
#pragma unroll
                for (int nt = 0; nt < 2; nt++) {
                    mma_bf16(C[nt], Ah, BH[sv][kt][nt]);
                    mma_bf16(C[nt], Ah, BL[sv][kt][nt]);
                    mma_bf16(C[nt], Al, BH[sv][kt][nt]);
                }
            }
            const int b2 = mt >> 1;
            const int nA = n0 + (mt & 1) * 16 + (lane >> 2);
            const int nB = nA + 8;
#pragma unroll
            for (int nt = 0; nt < 2; nt++) {
                const int v = (wid & 3) * 16 + nt * 8 + (lane & 3) * 2;
                float* dstA;
                float* dstB;
                if (wid < 4) {
                    if (b2 == 0) { dstA = g_ys + nA * 64 + v; dstB = g_ys + nB * 64 + v; }
                    else {
                        dstA = g_yv + nA * 192 + (b2 - 1) * 64 + v;
                        dstB = g_yv + nB * 192 + (b2 - 1) * 64 + v;
                    }
                } else {
                    if (b2 == 0) { dstA = g_scs + nA * 64 + v; dstB = g_scs + nB * 64 + v; }
                    else {
                        dstA = g_scv + nA * 192 + (b2 - 1) * 64 + v;
                        dstB = g_scv + nB * 192 + (b2 - 1) * 64 + v;
                    }
                }
                *(float2*)dstA = make_float2(C[nt][0], C[nt][1]);
                *(float2*)dstB = make_float2(C[nt][2], C[nt][3]);
            }
        }
    }
}

// ---------------- K2: edge MLP (stages 2+3 on mma.sync) + TP + scatter ------
// Tile metadata (ea/esh/ei) is register-prefetched one tile ahead; gathers
// prefetched before each half's mainloop; loop-top sync removed (epilogue's
// final sync already orders prior readers before next-tile smem writes).
#define SM_W1   0        // 512
#define SM_W2HI 512      // 2304
#define SM_W2LO 2816     // 2304
#define SM_H1HI 5120     // 4608
#define SM_H1LO 9728     // 4608
#define SM_AHI  14336    // 4608
#define SM_ALO  18944    // 4608
#define SM_WT   23552    // 64*264 = 16896
#define SM_EA   40448    // 1024
#define SM_SH   41472    // 512
#define SM_SD   41984    // 256 ints
#define K2_SMEM (42240 * 4)

__global__ __launch_bounds__(512, 1) void k_edge(
    const float* __restrict__ ea, const float* __restrict__ esh,
    const int* __restrict__ ei,
    const float* __restrict__ fw1, const float* __restrict__ fw2,
    const float* __restrict__ fw3)
{
    extern __shared__ float sm[];
    float* sW1 = sm + SM_W1;
    __nv_bfloat16* sW2hi = (__nv_bfloat16*)(sm + SM_W2HI);
    __nv_bfloat16* sW2lo = (__nv_bfloat16*)(sm + SM_W2LO);
    __nv_bfloat16* sH1hi = (__nv_bfloat16*)(sm + SM_H1HI);
    __nv_bfloat16* sH1lo = (__nv_bfloat16*)(sm + SM_H1LO);
    __nv_bfloat16* sAhi  = (__nv_bfloat16*)(sm + SM_AHI);
    __nv_bfloat16* sAlo  = (__nv_bfloat16*)(sm + SM_ALO);
    float* sWT = sm + SM_WT;
    float* sEA = sm + SM_EA;
    float* sSH = sm + SM_SH;
    int*   sSD = (int*)(sm + SM_SD);

    const int tid  = threadIdx.x;
    const int wid  = tid >> 5;
    const int lane = tid & 31;

    for (int i = tid; i < 512; i += 512) sW1[i] = fw1[i];
    for (int i = tid; i < 2048; i += 512) {
        int n = i >> 5, kp = i & 31;
        float x0 = fw2[(2 * kp) * 64 + n] * 0.125f;
        float x1 = fw2[(2 * kp + 1) * 64 + n] * 0.125f;
        unsigned hi, lo;
        split2(x0, x1, hi, lo);
        *(unsigned*)(sW2hi + n * 72 + kp * 2) = hi;
        *(unsigned*)(sW2lo + n * 72 + kp * 2) = lo;
    }

    unsigned Bhi[2][4][2], Blo[2][4][2];
    {
        const float inv8 = 0.125f;
        const int n = wid * 16 + (lane >> 2);
#pragma unroll
        for (int nt = 0; nt < 2; nt++) {
#pragma unroll
            for (int kt = 0; kt < 4; kt++) {
                int k0 = kt * 16 + (lane & 3) * 2;
                int nn = n + nt * 8;
                float x0 = fw3[k0 * 256 + nn] * inv8;
                float x1 = fw3[(k0 + 1) * 256 + nn] * inv8;
                split2(x0, x1, Bhi[nt][kt][0], Blo[nt][kt][0]);
                float x2 = fw3[(k0 + 8) * 256 + nn] * inv8;
                float x3 = fw3[(k0 + 9) * 256 + nn] * inv8;
                split2(x2, x3, Bhi[nt][kt][1], Blo[nt][kt][1]);
            }
        }
    }
    const unsigned laneoff =
        ((lane & 7) + ((lane >> 3) & 1) * 8) * 144 + (lane >> 4) * 16;
    const unsigned h1hiU = smem_u32(sH1hi);
    const unsigned h1loU = smem_u32(sH1lo);
    const unsigned ahiU  = smem_u32(sAhi);
    const unsigned aloU  = smem_u32(sAlo);
    const unsigned w2hiU = smem_u32(sW2hi);
    const unsigned w2loU = smem_u32(sW2lo);

    const float invs8 = 0.35355339059327373f;
    const float INV_SQRT3 = 0.5773502691896258f;
    const int NTILES = N_EDGES / 128;

    // --- register prefetch of tile metadata, one tile ahead ---
    float4 rEA, rSH;
    int rS = 0, rD = 0;
    int t = blockIdx.x;
    if (t < NTILES) {
        const int e0 = t * 128;
        if (tid < 256) rEA = ((const float4*)(ea + e0 * 8))[tid];
        if (tid < 128) {
            rSH = ((const float4*)(esh + e0 * 4))[tid];
            rS  = ei[e0 + tid];
            rD  = ei[N_EDGES + e0 + tid];
        }
    }
    __syncthreads();   // covers weight-tile writes above

    for (; t < NTILES; t += gridDim.x) {
        // store this tile's prefetched metadata
        if (tid < 256) ((float4*)sEA)[tid] = rEA;
        if (tid < 128) {
            ((float4*)sSH)[tid] = rSH;
            sSD[tid]       = rS;
            sSD[128 + tid] = rD;
            atomicAdd(&g_deg[rS], 1.0f);
        }
        __syncthreads();

        // issue next tile's loads now; consumed ~5K cycles later
        {
            const int tn = t + gridDim.x;
            if (tn < NTILES) {
                const int e0n = tn * 128;
                if (tid < 256) rEA = ((const float4*)(ea + e0n * 8))[tid];
                if (tid < 128) {
                    rSH = ((const float4*)(esh + e0n * 4))[tid];
                    rS  = ei[e0n + tid];
                    rD  = ei[N_EDGES + e0n + tid];
                }
            }
        }

        // ---- stage 1 -------------------------------------------------------
        {
            const int e = tid >> 2;
            const int q = tid & 3;
#pragma unroll
            for (int i = 0; i < 8; i++) {
                const int v0 = q * 16 + 2 * i;
                float a0 = 0.f, a1 = 0.f;
#pragma unroll
                for (int k = 0; k < 8; k++) {
                    float x = sEA[e * 8 + k];
                    a0 += x * sW1[k * 64 + v0];
                    a1 += x * sW1[k * 64 + v0 + 1];
                }
                a0 = silu(a0 * invs8);
                a1 = silu(a1 * invs8);
                unsigned hi, lo;
                split2(a0, a1, hi, lo);
                *(unsigned*)(sH1hi + e * 72 + v0) = hi;
                *(unsigned*)(sH1lo + e * 72 + v0) = lo;
            }
        }
        __syncthreads();

        // ---- stage 2 (mma bf16x3) ------------------------------------------
        {
            const int mtw = wid >> 1;
            const int ncb = (wid & 1) * 32;
            const int nb_l = ((lane >> 4) & 1) * 8 + (lane & 7);
            const int kb_l = ((lane >> 3) & 1) * 8;
            float C2[4][4];
#pragma unroll
            for (int nt = 0; nt < 4; nt++)
#pragma unroll
                for (int i = 0; i < 4; i++) C2[nt][i] = 0.f;
            const unsigned rowb = (unsigned)(mtw * 16 * 144) + laneoff;
#pragma unroll
            for (int kt = 0; kt < 4; kt++) {
                unsigned Ah[4], Al[4];
                ldsm4(Ah, h1hiU + rowb + kt * 32);
                ldsm4(Al, h1loU + rowb + kt * 32);
#pragma unroll
                for (int p = 0; p < 2; p++) {
                    unsigned off = (unsigned)((ncb + p * 16 + nb_l) * 144 +
                                              (kt * 16 + kb_l) * 2);
                    unsigned Bh[4], Bl[4];
                    ldsm4(Bh, w2hiU + off);
                    ldsm4(Bl, w2loU + off);
                    mma_bf16(C2[p * 2],     Ah, Bh);
                    mma_bf16(C2[p * 2],     Ah, Bl);
                    mma_bf16(C2[p * 2],     Al, Bh);
                    mma_bf16(C2[p * 2 + 1], Ah, Bh + 2);
                    mma_bf16(C2[p * 2 + 1], Ah, Bl + 2);
                    mma_bf16(C2[p * 2 + 1], Al, Bh + 2);
                }
            }
            const int r0 = mtw * 16 + (lane >> 2);
#pragma unroll
            for (int nt = 0; nt < 4; nt++) {
                int cc = ncb + nt * 8 + (lane & 3) * 2;
                float s0 = silu(C2[nt][0]), s1 = silu(C2[nt][1]);
                float s2 = silu(C2[nt][2]), s3 = silu(C2[nt][3]);
                unsigned h01, l01, h23, l23;
                split2(s0, s1, h01, l01);
                split2(s2, s3, h23, l23);
                *(unsigned*)(sAhi + r0 * 72 + cc) = h01;
                *(unsigned*)(sAlo + r0 * 72 + cc) = l01;
                *(unsigned*)(sAhi + (r0 + 8) * 72 + cc) = h23;
                *(unsigned*)(sAlo + (r0 + 8) * 72 + cc) = l23;
            }
        }
        __syncthreads();

        // ---- stage 3 + epilogue, two 64-edge halves ------------------------
#pragma unroll 1
        for (int half = 0; half < 2; half++) {
            const int ebh = half * 64;

            float4 pes[2], pev[2][3];
#pragma unroll
            for (int j = 0; j < 2; j++) {
                const int s = tid + 512 * j;
                const int el = s >> 4, vq = s & 15;
                const int dstn = sSD[128 + ebh + el];
                pes[j]    = *(const float4*)(g_ys + dstn * 64 + vq * 4);
                pev[j][0] = *(const float4*)(g_yv + dstn * 192 +       vq * 4);
                pev[j][1] = *(const float4*)(g_yv + dstn * 192 +  64 + vq * 4);
                pev[j][2] = *(const float4*)(g_yv + dstn * 192 + 128 + vq * 4);
            }

            float C[4][2][4];
#pragma unroll
            for (int mt = 0; mt < 4; mt++)
#pragma unroll
                for (int nt = 0; nt < 2; nt++)
#pragma unroll
                    for (int i = 0; i < 4; i++) C[mt][nt][i] = 0.f;

#pragma unroll
            for (int mt = 0; mt < 4; mt++) {
                const unsigned rowb = (unsigned)((ebh + mt * 16) * 144) + laneoff;
#pragma unroll
                for (int kt = 0; kt < 4; kt++) {
                    unsigned Ah[4], Al[4];
                    ldsm4(Ah, ahiU + rowb + kt * 32);
                    ldsm4(Al, aloU + rowb + kt * 32);
#pragma unroll
                    for (int nt = 0; nt < 2; nt++) {
                        mma_bf16(C[mt][nt], Ah, Bhi[nt][kt]);
                        mma_bf16(C[mt][nt], Ah, Blo[nt][kt]);
                        mma_bf16(C[mt][nt], Al, Bhi[nt][kt]);
                    }
                }
            }
#pragma unroll
            for (int mt = 0; mt < 4; mt++) {
#pragma unroll
                for (int nt = 0; nt < 2; nt++) {
                    int r = mt * 16 + (lane >> 2);
                    int cc = wid * 16 + nt * 8 + (lane & 3) * 2;
                    *(float2*)(sWT + r * 264 + cc) = make_float2(C[mt][nt][0], C[mt][nt][1]);
                    *(float2*)(sWT + (r + 8) * 264 + cc) = make_float2(C[mt][nt][2], C[mt][nt][3]);
                }
            }
            __syncthreads();

#pragma unroll
            for (int j = 0; j < 2; j++) {
                const int s = tid + 512 * j;
                const int el = s >> 4, vq = s & 15;
                const int eg = ebh + el;
                const float4 wA = *(const float4*)(sWT + el * 264 + vq * 4);
                const float4 wB = *(const float4*)(sWT + el * 264 + 64 + vq * 4);
                const float4 wC = *(const float4*)(sWT + el * 264 + 128 + vq * 4);
                const float4 wD = *(const float4*)(sWT + el * 264 + 192 + vq * 4);
                const int src = sSD[eg];
                const float sh0 = sSH[eg * 4];
                const float s1x = sSH[eg * 4 + 1], s1y = sSH[eg * 4 + 2], s1z = sSH[eg * 4 + 3];

                const float4 es  = pes[j];
                const float4 ev0 = pev[j][0];
                const float4 ev1 = pev[j][1];
                const float4 ev2 = pev[j][2];

                red4(g_ns + src * 128 + vq * 4,
                     wA.x * es.x * sh0, wA.y * es.y * sh0,
                     wA.z * es.z * sh0, wA.w * es.w * sh0);
                float4 dv;
                dv.x = ev0.x * s1x + ev1.x * s1y + ev2.x * s1z;
                dv.y = ev0.y * s1x + ev1.y * s1y + ev2.y * s1z;
                dv.z = ev0.z * s1x + ev1.z * s1y + ev2.z * s1z;
                dv.w = ev0.w * s1x + ev1.w * s1y + ev2.w * s1z;
                red4(g_ns + src * 128 + 64 + vq * 4,
                     wD.x * dv.x * INV_SQRT3, wD.y * dv.y * INV_SQRT3,
                     wD.z * dv.z * INV_SQRT3, wD.w * dv.w * INV_SQRT3);
                float4 be = make_float4(wB.x * es.x, wB.y * es.y, wB.z * es.z, wB.w * es.w);
                float* b = g_nv + src * 384 + vq * 4;
                red4(b,       be.x * s1x, be.y * s1x, be.z * s1x, be.w * s1x);
                red4(b + 128, be.x * s1y, be.y * s1y, be.z * s1y, be.w * s1y);
                red4(b + 256, be.x * s1z, be.y * s1z, be.z * s1z, be.w * s1z);
                float* b2 = g_nv + src * 384 + 64 + vq * 4;
                red4(b2,       wC.x * ev0.x * sh0, wC.y * ev0.y * sh0,
                               wC.z * ev0.z * sh0, wC.w * ev0.w * sh0);
                red4(b2 + 128, wC.x * ev1.x * sh0, wC.y * ev1.y * sh0,
                               wC.z * ev1.z * sh0, wC.w * ev1.w * sh0);
                red4(b2 + 256, wC.x * ev2.x * sh0, wC.y * ev2.y * sh0,
                               wC.z * ev2.z * sh0, wC.w * ev2.w * sh0);
            }
            __syncthreads();
        }
    }
}

// ---------------- K3: output GEMM + residual + RMS norm (FFMA2, R11) --------
#define K3W 8576
#define K3_SMEM ((2 * K3W + 16 * 128 + 16 * 384) * 4)
__global__ __launch_bounds__(256, 2) void k_node_out(
    const float* __restrict__ w2s, const float* __restrict__ w2v,
    const float* __restrict__ gs, const float* __restrict__ gv,
    float* __restrict__ out)
{
    extern __shared__ float sm[];
    float* sWsT = sm;                 // [32][268]
    float* sWvT = sm + K3W;
    float* sNs  = sm + 2 * K3W;
    float* sNv  = sm + 2 * K3W + 2048;

    const int tid = threadIdx.x;
    for (int i = tid; i < 8192; i += 256) {
        int u = i >> 6, v = i & 63;
        sWsT[(v >> 1) * 268 + u * 2 + (v & 1)] = w2s[i];
        sWvT[(v >> 1) * 268 + u * 2 + (v & 1)] = w2v[i];
    }

    const int vt   = tid & 31;
    const int warp = tid >> 5;
    const float inv2 = 0.08838834764831845f;

    for (int t = blockIdx.x; t < N_NODES / 16; t += gridDim.x) {
        __syncthreads();
        const int n0 = t * 16;
        for (int i = tid; i < 512; i += 256)
            ((float4*)sNs)[i] = ((const float4*)g_ns)[n0 * 32 + i];
        for (int i = tid; i < 1536; i += 256)
            ((float4*)sNv)[i] = ((const float4*)g_nv)[n0 * 96 + i];
        __syncthreads();

        ull oS[2] = {0ull, 0ull};
        ull oV[2][3] = {{0ull,0ull,0ull},{0ull,0ull,0ull}};
        for (int u = 0; u < 128; u += 2) {
            ulonglong2 wsp = *(const ulonglong2*)(sWsT + vt * 268 + u * 2);
            ulonglong2 wvp = *(const ulonglong2*)(sWvT + vt * 268 + u * 2);
#pragma unroll
            for (int k = 0; k < 2; k++) {
                int n = warp * 2 + k;
                float2 xs2 = *(const float2*)(sNs + n * 128 + u);
                oS[k] = ffma2(bcast2(xs2.x), wsp.x, oS[k]);
                oS[k] = ffma2(bcast2(xs2.y), wsp.y, oS[k]);
#pragma unroll
                for (int d = 0; d < 3; d++) {
                    float2 xv2 = *(const float2*)(sNv + n * 384 + d * 128 + u);
                    oV[k][d] = ffma2(bcast2(xv2.x), wvp.x, oV[k][d]);
                    oV[k][d] = ffma2(bcast2(xv2.y), wvp.y, oV[k][d]);
                }
            }
        }

#pragma unroll
        for (int k = 0; k < 2; k++) {
            const int n = n0 + warp * 2 + k;
            const float dn = rsqrtf(fmaxf(g_deg[n], 1.0f)) * inv2;
            float s0, s1;
            unpack2(oS[k], s0, s1);
            float2 scs = *(const float2*)(g_scs + n * 64 + vt * 2);
            s0 = s0 * dn + scs.x;
            s1 = s1 * dn + scs.y;
            float v0[3], v1[3];
            float vsum = 0.f;
#pragma unroll
            for (int d = 0; d < 3; d++) {
                float a, b;
                unpack2(oV[k][d], a, b);
                float2 scv = *(const float2*)(g_scv + n * 192 + d * 64 + vt * 2);
                a = a * dn + scv.x;
                b = b * dn + scv.y;
                v0[d] = a; v1[d] = b;
                vsum += a * a + b * b;
            }
            float ssum = s0 * s0 + s1 * s1;
#pragma unroll
            for (int off = 16; off; off >>= 1) {
                ssum += __shfl_xor_sync(0xffffffffu, ssum, off);
                vsum += __shfl_xor_sync(0xffffffffu, vsum, off);
            }
            const float rs = rsqrtf(ssum * (1.0f / 64.0f)  + 1e-5f);
            const float rv = rsqrtf(vsum * (1.0f / 192.0f) + 1e-5f);
            *(float2*)(out + n * 256 + vt * 2) =
                make_float2(s0 * rs * gs[vt * 2], s1 * rs * gs[vt * 2 + 1]);
            const float gv0 = gv[vt * 2] * rv, gv1 = gv[vt * 2 + 1] * rv;
#pragma unroll
            for (int d = 0; d < 3; d++) {
                out[n * 256 + 64 + (vt * 2)     * 3 + d] = v0[d] * gv0;
                out[n * 256 + 64 + (vt * 2 + 1) * 3 + d] = v1[d] * gv1;
            }
        }
    }
}

// ---------------- launcher ----------------------------------------------------
extern "C" void kernel_launch(void* const* d_in, const int* in_sizes, int n_in,
                              void* d_out, int out_size)
{
    const float* nh   = (const float*)d_in[0];
    const float* ea   = (const float*)d_in[1];
    const float* esh  = (const float*)d_in[2];
    const float* w1s  = (const float*)d_in[3];
    const float* w1v  = (const float*)d_in[4];
    const float* wscs = (const float*)d_in[5];
    const float* wscv = (const float*)d_in[6];
    const float* w2s  = (const float*)d_in[7];
    const float* w2v  = (const float*)d_in[8];
    const float* fw1  = (const float*)d_in[9];
    const float* fw2  = (const float*)d_in[10];
    const float* fw3  = (const float*)d_in[11];
    const float* gs   = (const float*)d_in[12];
    const float* gv   = (const float*)d_in[13];
    const int*   eidx = (const int*)d_in[14];
    float* out = (float*)d_out;

    cudaFuncSetAttribute(k_node_in,  cudaFuncAttributeMaxDynamicSharedMemorySize, K1_SMEM);
    cudaFuncSetAttribute(k_edge,     cudaFuncAttributeMaxDynamicSharedMemorySize, K2_SMEM);
    cudaFuncSetAttribute(k_node_out, cudaFuncAttributeMaxDynamicSharedMemorySize, K3_SMEM);

    k_node_in<<<296, 256, K1_SMEM>>>(nh, w1s, w1v, wscs, wscv);
    k_edge<<<148, 512, K2_SMEM>>>(ea, esh, eidx, fw1, fw2, fw3);
    k_node_out<<<296, 256, K3_SMEM>>>(w2s, w2v, gs, gv, out);
}

// round 15
// speedup vs baseline: 1.0734x; 1.0107x over previous
#include <cuda_runtime.h>
#include <cuda_bf16.h>
#include <math.h>

#define N_NODES 20000
#define N_EDGES 320000

// ---------------- scratch (device globals) ----------------------------------
__device__ __align__(16) float g_ys [N_NODES * 64];
__device__ __align__(16) float g_yv [N_NODES * 192];
__device__ __align__(16) float g_scs[N_NODES * 64];
__device__ __align__(16) float g_scv[N_NODES * 192];
__device__ __align__(16) float g_ns [N_NODES * 128];
__device__ __align__(16) float g_nv [N_NODES * 384];
__device__ __align__(16) float g_deg[N_NODES];

typedef unsigned long long ull;

// ---------------- helpers ----------------------------------------------------
__device__ __forceinline__ void red4(float* p, float x, float y, float z, float w) {
    asm volatile("red.global.add.v4.f32 [%0], {%1,%2,%3,%4};"
                 :: "l"(p), "f"(x), "f"(y), "f"(z), "f"(w) : "memory");
}
__device__ __forceinline__ float silu(float x) {
    return x * (1.0f / (1.0f + __expf(-x)));
}
__device__ __forceinline__ ull ffma2(ull a, ull b, ull c) {
    ull d;
    asm("fma.rn.f32x2 %0, %1, %2, %3;" : "=l"(d) : "l"(a), "l"(b), "l"(c));
    return d;
}
__device__ __forceinline__ ull bcast2(float x) {
    ull r;
    asm("mov.b64 %0, {%1, %1};" : "=l"(r) : "f"(x));
    return r;
}
__device__ __forceinline__ void unpack2(ull p, float& x, float& y) {
    asm("mov.b64 {%0, %1}, %2;" : "=f"(x), "=f"(y) : "l"(p));
}
__device__ __forceinline__ unsigned smem_u32(const void* p) {
    unsigned a;
    asm("{ .reg .u64 t; cvta.to.shared.u64 t, %1; cvt.u32.u64 %0, t; }"
        : "=r"(a) : "l"(p));
    return a;
}
__device__ __forceinline__ void split2(float a, float b, unsigned& hi, unsigned& lo) {
    __nv_bfloat162 H, L;
    H.x = __float2bfloat16(a);
    H.y = __float2bfloat16(b);
    L.x = __float2bfloat16(a - __bfloat162float(H.x));
    L.y = __float2bfloat16(b - __bfloat162float(H.y));
    hi = *(unsigned*)&H;
    lo = *(unsigned*)&L;
}
__device__ __forceinline__ void mma_bf16(float* c, const unsigned* a, const unsigned* b) {
    asm volatile(
        "mma.sync.aligned.m16n8k16.row.col.f32.bf16.bf16.f32 "
        "{%0,%1,%2,%3}, {%4,%5,%6,%7}, {%8,%9}, {%0,%1,%2,%3};"
        : "+f"(c[0]), "+f"(c[1]), "+f"(c[2]), "+f"(c[3])
        : "r"(a[0]), "r"(a[1]), "r"(a[2]), "r"(a[3]), "r"(b[0]), "r"(b[1]));
}
__device__ __forceinline__ void ldsm4(unsigned* r, unsigned addr) {
    asm volatile("ldmatrix.sync.aligned.m8n8.x4.shared.b16 {%0,%1,%2,%3}, [%4];"
                 : "=r"(r[0]), "=r"(r[1]), "=r"(r[2]), "=r"(r[3]) : "r"(addr));
}

// ---------------- K1: zero scratch + node input transforms (mma bf16x3) -----
#define K1_SX   0
#define K1_AHI  8224
#define K1_ALO  12832
#define K1_SMEM (17440 * 4)
__global__ __launch_bounds__(256, 2) void k_node_in(
    const float* __restrict__ nh,
    const float* __restrict__ w1s, const float* __restrict__ w1v,
    const float* __restrict__ wscs, const float* __restrict__ wscv)
{
    extern __shared__ float sm[];
    float* sX = sm + K1_SX;                              // [32][257]
    __nv_bfloat16* sAhi = (__nv_bfloat16*)(sm + K1_AHI); // [128][72]
    __nv_bfloat16* sAlo = (__nv_bfloat16*)(sm + K1_ALO);

    const int tid  = threadIdx.x;
    const int wid  = tid >> 5;
    const int lane = tid & 31;

    {
        int gi = blockIdx.x * blockDim.x + tid;
        int gstr = gridDim.x * blockDim.x;
        float4 z = make_float4(0.f, 0.f, 0.f, 0.f);
        for (int j = gi; j < N_NODES * 128 / 4; j += gstr) ((float4*)g_ns)[j] = z;
        for (int j = gi; j < N_NODES * 384 / 4; j += gstr) ((float4*)g_nv)[j] = z;
        for (int j = gi; j < N_NODES; j += gstr) g_deg[j] = 0.f;
    }

    unsigned BH[2][4][2][2], BL[2][4][2][2];
    {
        const float inv = 0.125f;
        const float* srcS = (wid < 4) ? w1s : wscs;
        const float* srcV = (wid < 4) ? w1v : wscv;
        const int nc = (wid & 3) * 16 + (lane >> 2);
#pragma unroll
        for (int sv = 0; sv < 2; sv++) {
            const float* src = sv ? srcV : srcS;
#pragma unroll
            for (int nt = 0; nt < 2; nt++) {
#pragma unroll
                for (int kt = 0; kt < 4; kt++) {
                    int k0 = kt * 16 + (lane & 3) * 2;
                    int nn = nc + nt * 8;
                    float x0 = src[k0 * 64 + nn] * inv;
                    float x1 = src[(k0 + 1) * 64 + nn] * inv;
                    split2(x0, x1, BH[sv][kt][nt][0], BL[sv][kt][nt][0]);
                    float x2 = src[(k0 + 8) * 64 + nn] * inv;
                    float x3 = src[(k0 + 9) * 64 + nn] * inv;
                    split2(x2, x3, BH[sv][kt][nt][1], BL[sv][kt][nt][1]);
                }
            }
        }
    }
    const unsigned laneoff =
        ((lane & 7) + ((lane >> 3) & 1) * 8) * 144 + (lane >> 4) * 16;
    const unsigned ahiU = smem_u32(sAhi);
    const unsigned aloU = smem_u32(sAlo);

    for (int t = blockIdx.x; t < N_NODES / 32; t += gridDim.x) {
        __syncthreads();
        const int n0 = t * 32;
        for (int i = tid; i < 32 * 256; i += 256) {
            int n = i >> 8, c = i & 255;
            sX[n * 257 + c] = nh[(n0 + n) * 256 + c];
        }
        __syncthreads();

        {
            const int r = tid >> 1;
            const int b = r >> 5;
            const float* base = sX + (r & 31) * 257;
            const int ch = (tid & 1) * 16;
#pragma unroll
            for (int c = 0; c < 16; c++) {
                int cp = ch + c;
                float x0, x1;
                if (b == 0) {
                    x0 = base[2 * cp];
                    x1 = base[2 * cp + 1];
                } else {
                    x0 = base[64 + (2 * cp) * 3 + (b - 1)];
                    x1 = base[64 + (2 * cp + 1) * 3 + (b - 1)];
                }
                unsigned hi, lo;
                split2(x0, x1, hi, lo);
                *(unsigned*)(sAhi + r * 72 + cp * 2) = hi;
                *(unsigned*)(sAlo + r * 72 + cp * 2) = lo;
            }
        }
        __syncthreads();

#pragma unroll
        for (int mt = 0; mt < 8; mt++) {
            const int sv = (mt < 2) ? 0 : 1;
            const unsigned rowb = (unsigned)(mt * 16 * 144) + laneoff;
            float C[2][4];
#pragma unroll
            for (int nt = 0; nt < 2; nt++)
#pragma unroll
                for (int i = 0; i < 4; i++) C[nt][i] = 0.f;
#pragma unroll
            for (int kt = 0; kt < 4; kt++) {
                unsigned Ah[4], Al[4];
                ldsm4(Ah, ahiU + rowb + kt * 32);
                ldsm4(Al, aloU + rowb + kt * 32);
#pragma unroll
                for (int nt = 0; nt < 2; nt++) {
                    mma_bf16(C[nt], Ah, BH[sv][kt][nt]);
                    mma_bf16(C[nt], Ah, BL[sv][kt][nt]);
                    mma_bf16(C[nt], Al, BH[sv][kt][nt]);
                }
            }
            const int b2 = mt >> 1;
            const int nA = n0 + (mt & 1) * 16 + (lane >> 2);
            const int nB = nA + 8;
#pragma unroll
            for (int nt = 0; nt < 2; nt++) {
                const int v = (wid & 3) * 16 + nt * 8 + (lane & 3) * 2;
                float* dstA;
                float* dstB;
                if (wid < 4) {
                    if (b2 == 0) { dstA = g_ys + nA * 64 + v; dstB = g_ys + nB * 64 + v; }
                    else {
                        dstA = g_yv + nA * 192 + (b2 - 1) * 64 + v;
                        dstB = g_yv + nB * 192 + (b2 - 1) * 64 + v;
                    }
                } else {
                    if (b2 == 0) { dstA = g_scs + nA * 64 + v; dstB = g_scs + nB * 64 + v; }
                    else {
                        dstA = g_scv + nA * 192 + (b2 - 1) * 64 + v;
                        dstB = g_scv + nB * 192 + (b2 - 1) * 64 + v;
                    }
                }
                *(float2*)dstA = make_float2(C[nt][0], C[nt][1]);
                *(float2*)dstB = make_float2(C[nt][2], C[nt][3]);
            }
        }
    }
}

// ---------------- K2: edge MLP (stages 2+3 on mma.sync) + TP + scatter ------
// (unchanged from R14 best: metadata register-prefetch, gather prefetch,
// 6 syncs/tile)
#define SM_W1   0        // 512
#define SM_W2HI 512      // 2304
#define SM_W2LO 2816     // 2304
#define SM_H1HI 5120     // 4608
#define SM_H1LO 9728     // 4608
#define SM_AHI  14336    // 4608
#define SM_ALO  18944    // 4608
#define SM_WT   23552    // 64*264 = 16896
#define SM_EA   40448    // 1024
#define SM_SH   41472    // 512
#define SM_SD   41984    // 256 ints
#define K2_SMEM (42240 * 4)

__global__ __launch_bounds__(512, 1) void k_edge(
    const float* __restrict__ ea, const float* __restrict__ esh,
    const int* __restrict__ ei,
    const float* __restrict__ fw1, const float* __restrict__ fw2,
    const float* __restrict__ fw3)
{
    extern __shared__ float sm[];
    float* sW1 = sm + SM_W1;
    __nv_bfloat16* sW2hi = (__nv_bfloat16*)(sm + SM_W2HI);
    __nv_bfloat16* sW2lo = (__nv_bfloat16*)(sm + SM_W2LO);
    __nv_bfloat16* sH1hi = (__nv_bfloat16*)(sm + SM_H1HI);
    __nv_bfloat16* sH1lo = (__nv_bfloat16*)(sm + SM_H1LO);
    __nv_bfloat16* sAhi  = (__nv_bfloat16*)(sm + SM_AHI);
    __nv_bfloat16* sAlo  = (__nv_bfloat16*)(sm + SM_ALO);
    float* sWT = sm + SM_WT;
    float* sEA = sm + SM_EA;
    float* sSH = sm + SM_SH;
    int*   sSD = (int*)(sm + SM_SD);

    const int tid  = threadIdx.x;
    const int wid  = tid >> 5;
    const int lane = tid & 31;

    for (int i = tid; i < 512; i += 512) sW1[i] = fw1[i];
    for (int i = tid; i < 2048; i += 512) {
        int n = i >> 5, kp = i & 31;
        float x0 = fw2[(2 * kp) * 64 + n] * 0.125f;
        float x1 = fw2[(2 * kp + 1) * 64 + n] * 0.125f;
        unsigned hi, lo;
        split2(x0, x1, hi, lo);
        *(unsigned*)(sW2hi + n * 72 + kp * 2) = hi;
        *(unsigned*)(sW2lo + n * 72 + kp * 2) = lo;
    }

    unsigned Bhi[2][4][2], Blo[2][4][2];
    {
        const float inv8 = 0.125f;
        const int n = wid * 16 + (lane >> 2);
#pragma unroll
        for (int nt = 0; nt < 2; nt++) {
#pragma unroll
            for (int kt = 0; kt < 4; kt++) {
                int k0 = kt * 16 + (lane & 3) * 2;
                int nn = n + nt * 8;
                float x0 = fw3[k0 * 256 + nn] * inv8;
                float x1 = fw3[(k0 + 1) * 256 + nn] * inv8;
                split2(x0, x1, Bhi[nt][kt][0], Blo[nt][kt][0]);
                float x2 = fw3[(k0 + 8) * 256 + nn] * inv8;
                float x3 = fw3[(k0 + 9) * 256 + nn] * inv8;
                split2(x2, x3, Bhi[nt][kt][1], Blo[nt][kt][1]);
            }
        }
    }
    const unsigned laneoff =
        ((lane & 7) + ((lane >> 3) & 1) * 8) * 144 + (lane >> 4) * 16;
    const unsigned h1hiU = smem_u32(sH1hi);
    const unsigned h1loU = smem_u32(sH1lo);
    const unsigned ahiU  = smem_u32(sAhi);
    const unsigned aloU  = smem_u32(sAlo);
    const unsigned w2hiU = smem_u32(sW2hi);
    const unsigned w2loU = smem_u32(sW2lo);

    const float invs8 = 0.35355339059327373f;
    const float INV_SQRT3 = 0.5773502691896258f;
    const int NTILES = N_EDGES / 128;

    float4 rEA, rSH;
    int rS = 0, rD = 0;
    int t = blockIdx.x;
    if (t < NTILES) {
        const int e0 = t * 128;
        if (tid < 256) rEA = ((const float4*)(ea + e0 * 8))[tid];
        if (tid < 128) {
            rSH = ((const float4*)(esh + e0 * 4))[tid];
            rS  = ei[e0 + tid];
            rD  = ei[N_EDGES + e0 + tid];
        }
    }
    __syncthreads();

    for (; t < NTILES; t += gridDim.x) {
        if (tid < 256) ((float4*)sEA)[tid] = rEA;
        if (tid < 128) {
            ((float4*)sSH)[tid] = rSH;
            sSD[tid]       = rS;
            sSD[128 + tid] = rD;
            atomicAdd(&g_deg[rS], 1.0f);
        }
        __syncthreads();

        {
            const int tn = t + gridDim.x;
            if (tn < NTILES) {
                const int e0n = tn * 128;
                if (tid < 256) rEA = ((const float4*)(ea + e0n * 8))[tid];
                if (tid < 128) {
                    rSH = ((const float4*)(esh + e0n * 4))[tid];
                    rS  = ei[e0n + tid];
                    rD  = ei[N_EDGES + e0n + tid];
                }
            }
        }

        // ---- stage 1 -------------------------------------------------------
        {
            const int e = tid >> 2;
            const int q = tid & 3;
#pragma unroll
            for (int i = 0; i < 8; i++) {
                const int v0 = q * 16 + 2 * i;
                float a0 = 0.f, a1 = 0.f;
#pragma unroll
                for (int k = 0; k < 8; k++) {
                    float x = sEA[e * 8 + k];
                    a0 += x * sW1[k * 64 + v0];
                    a1 += x * sW1[k * 64 + v0 + 1];
                }
                a0 = silu(a0 * invs8);
                a1 = silu(a1 * invs8);
                unsigned hi, lo;
                split2(a0, a1, hi, lo);
                *(unsigned*)(sH1hi + e * 72 + v0) = hi;
                *(unsigned*)(sH1lo + e * 72 + v0) = lo;
            }
        }
        __syncthreads();

        // ---- stage 2 (mma bf16x3) ------------------------------------------
        {
            const int mtw = wid >> 1;
            const int ncb = (wid & 1) * 32;
            const int nb_l = ((lane >> 4) & 1) * 8 + (lane & 7);
            const int kb_l = ((lane >> 3) & 1) * 8;
            float C2[4][4];
#pragma unroll
            for (int nt = 0; nt < 4; nt++)
#pragma unroll
                for (int i = 0; i < 4; i++) C2[nt][i] = 0.f;
            const unsigned rowb = (unsigned)(mtw * 16 * 144) + laneoff;
#pragma unroll
            for (int kt = 0; kt < 4; kt++) {
                unsigned Ah[4], Al[4];
                ldsm4(Ah, h1hiU + rowb + kt * 32);
                ldsm4(Al, h1loU + rowb + kt * 32);
#pragma unroll
                for (int p = 0; p < 2; p++) {
                    unsigned off = (unsigned)((ncb + p * 16 + nb_l) * 144 +
                                              (kt * 16 + kb_l) * 2);
                    unsigned Bh[4], Bl[4];
                    ldsm4(Bh, w2hiU + off);
                    ldsm4(Bl, w2loU + off);
                    mma_bf16(C2[p * 2],     Ah, Bh);
                    mma_bf16(C2[p * 2],     Ah, Bl);
                    mma_bf16(C2[p * 2],     Al, Bh);
                    mma_bf16(C2[p * 2 + 1], Ah, Bh + 2);
                    mma_bf16(C2[p * 2 + 1], Ah, Bl + 2);
                    mma_bf16(C2[p * 2 + 1], Al, Bh + 2);
                }
            }
            const int r0 = mtw * 16 + (lane >> 2);
#pragma unroll
            for (int nt = 0; nt < 4; nt++) {
                int cc = ncb + nt * 8 + (lane & 3) * 2;
                float s0 = silu(C2[nt][0]), s1 = silu(C2[nt][1]);
                float s2 = silu(C2[nt][2]), s3 = silu(C2[nt][3]);
                unsigned h01, l01, h23, l23;
                split2(s0, s1, h01, l01);
                split2(s2, s3, h23, l23);
                *(unsigned*)(sAhi + r0 * 72 + cc) = h01;
                *(unsigned*)(sAlo + r0 * 72 + cc) = l01;
                *(unsigned*)(sAhi + (r0 + 8) * 72 + cc) = h23;
                *(unsigned*)(sAlo + (r0 + 8) * 72 + cc) = l23;
            }
        }
        __syncthreads();

        // ---- stage 3 + epilogue, two 64-edge halves ------------------------
#pragma unroll 1
        for (int half = 0; half < 2; half++) {
            const int ebh = half * 64;

            float4 pes[2], pev[2][3];
#pragma unroll
            for (int j = 0; j < 2; j++) {
                const int s = tid + 512 * j;
                const int el = s >> 4, vq = s & 15;
                const int dstn = sSD[128 + ebh + el];
                pes[j]    = *(const float4*)(g_ys + dstn * 64 + vq * 4);
                pev[j][0] = *(const float4*)(g_yv + dstn * 192 +       vq * 4);
                pev[j][1] = *(const float4*)(g_yv + dstn * 192 +  64 + vq * 4);
                pev[j][2] = *(const float4*)(g_yv + dstn * 192 + 128 + vq * 4);
            }

            float C[4][2][4];
#pragma unroll
            for (int mt = 0; mt < 4; mt++)
#pragma unroll
                for (int nt = 0; nt < 2; nt++)
#pragma unroll
                    for (int i = 0; i < 4; i++) C[mt][nt][i] = 0.f;

#pragma unroll
            for (int mt = 0; mt < 4; mt++) {
                const unsigned rowb = (unsigned)((ebh + mt * 16) * 144) + laneoff;
#pragma unroll
                for (int kt = 0; kt < 4; kt++) {
                    unsigned Ah[4], Al[4];
                    ldsm4(Ah, ahiU + rowb + kt * 32);
                    ldsm4(Al, aloU + rowb + kt * 32);
#pragma unroll
                    for (int nt = 0; nt < 2; nt++) {
                        mma_bf16(C[mt][nt], Ah, Bhi[nt][kt]);
                        mma_bf16(C[mt][nt], Ah, Blo[nt][kt]);
                        mma_bf16(C[mt][nt], Al, Bhi[nt][kt]);
                    }
                }
            }
#pragma unroll
            for (int mt = 0; mt < 4; mt++) {
#pragma unroll
                for (int nt = 0; nt < 2; nt++) {
                    int r = mt * 16 + (lane >> 2);
                    int cc = wid * 16 + nt * 8 + (lane & 3) * 2;
                    *(float2*)(sWT + r * 264 + cc) = make_float2(C[mt][nt][0], C[mt][nt][1]);
                    *(float2*)(sWT + (r + 8) * 264 + cc) = make_float2(C[mt][nt][2], C[mt][nt][3]);
                }
            }
            __syncthreads();

#pragma unroll
            for (int j = 0; j < 2; j++) {
                const int s = tid + 512 * j;
                const int el = s >> 4, vq = s & 15;
                const int eg = ebh + el;
                const float4 wA = *(const float4*)(sWT + el * 264 + vq * 4);
                const float4 wB = *(const float4*)(sWT + el * 264 + 64 + vq * 4);
                const float4 wC = *(const float4*)(sWT + el * 264 + 128 + vq * 4);
                const float4 wD = *(const float4*)(sWT + el * 264 + 192 + vq * 4);
                const int src = sSD[eg];
                const float sh0 = sSH[eg * 4];
                const float s1x = sSH[eg * 4 + 1], s1y = sSH[eg * 4 + 2], s1z = sSH[eg * 4 + 3];

                const float4 es  = pes[j];
                const float4 ev0 = pev[j][0];
                const float4 ev1 = pev[j][1];
                const float4 ev2 = pev[j][2];

                red4(g_ns + src * 128 + vq * 4,
                     wA.x * es.x * sh0, wA.y * es.y * sh0,
                     wA.z * es.z * sh0, wA.w * es.w * sh0);
                float4 dv;
                dv.x = ev0.x * s1x + ev1.x * s1y + ev2.x * s1z;
                dv.y = ev0.y * s1x + ev1.y * s1y + ev2.y * s1z;
                dv.z = ev0.z * s1x + ev1.z * s1y + ev2.z * s1z;
                dv.w = ev0.w * s1x + ev1.w * s1y + ev2.w * s1z;
                red4(g_ns + src * 128 + 64 + vq * 4,
                     wD.x * dv.x * INV_SQRT3, wD.y * dv.y * INV_SQRT3,
                     wD.z * dv.z * INV_SQRT3, wD.w * dv.w * INV_SQRT3);
                float4 be = make_float4(wB.x * es.x, wB.y * es.y, wB.z * es.z, wB.w * es.w);
                float* b = g_nv + src * 384 + vq * 4;
                red4(b,       be.x * s1x, be.y * s1x, be.z * s1x, be.w * s1x);
                red4(b + 128, be.x * s1y, be.y * s1y, be.z * s1y, be.w * s1y);
                red4(b + 256, be.x * s1z, be.y * s1z, be.z * s1z, be.w * s1z);
                float* b2 = g_nv + src * 384 + 64 + vq * 4;
                red4(b2,       wC.x * ev0.x * sh0, wC.y * ev0.y * sh0,
                               wC.z * ev0.z * sh0, wC.w * ev0.w * sh0);
                red4(b2 + 128, wC.x * ev1.x * sh0, wC.y * ev1.y * sh0,
                               wC.z * ev1.z * sh0, wC.w * ev1.w * sh0);
                red4(b2 + 256, wC.x * ev2.x * sh0, wC.y * ev2.y * sh0,
                               wC.z * ev2.z * sh0, wC.w * ev2.w * sh0);
            }
            __syncthreads();
        }
    }
}

// ---------------- K3: output GEMM + residual + RMS norm (FFMA2) -------------
// R14 K3 + register-prefetch of next tile's ns/nv (R14-proven pattern).
#define K3W 8576
#define K3_SMEM ((2 * K3W + 16 * 128 + 16 * 384) * 4)
__global__ __launch_bounds__(256, 2) void k_node_out(
    const float* __restrict__ w2s, const float* __restrict__ w2v,
    const float* __restrict__ gs, const float* __restrict__ gv,
    float* __restrict__ out)
{
    extern __shared__ float sm[];
    float* sWsT = sm;                 // [32][268]
    float* sWvT = sm + K3W;
    float* sNs  = sm + 2 * K3W;
    float* sNv  = sm + 2 * K3W + 2048;

    const int tid = threadIdx.x;
    for (int i = tid; i < 8192; i += 256) {
        int u = i >> 6, v = i & 63;
        sWsT[(v >> 1) * 268 + u * 2 + (v & 1)] = w2s[i];
        sWvT[(v >> 1) * 268 + u * 2 + (v & 1)] = w2v[i];
    }

    const int vt   = tid & 31;
    const int warp = tid >> 5;
    const float inv2 = 0.08838834764831845f;
    const int NT3 = N_NODES / 16;

    // register-prefetch first tile
    float4 rNs[2], rNv[6];
    int t = blockIdx.x;
    if (t < NT3) {
        const int n0 = t * 16;
        rNs[0] = ((const float4*)g_ns)[n0 * 32 + tid];
        rNs[1] = ((const float4*)g_ns)[n0 * 32 + tid + 256];
#pragma unroll
        for (int i = 0; i < 6; i++)
            rNv[i] = ((const float4*)g_nv)[n0 * 96 + tid + 256 * i];
    }
    __syncthreads();   // weight staging complete

    for (; t < NT3; t += gridDim.x) {
        const int n0 = t * 16;
        ((float4*)sNs)[tid]       = rNs[0];
        ((float4*)sNs)[tid + 256] = rNs[1];
#pragma unroll
        for (int i = 0; i < 6; i++) ((float4*)sNv)[tid + 256 * i] = rNv[i];
        __syncthreads();

        // prefetch next tile while GEMM runs
        {
            const int tn = t + gridDim.x;
            if (tn < NT3) {
                const int n0n = tn * 16;
                rNs[0] = ((const float4*)g_ns)[n0n * 32 + tid];
                rNs[1] = ((const float4*)g_ns)[n0n * 32 + tid + 256];
#pragma unroll
                for (int i = 0; i < 6; i++)
                    rNv[i] = ((const float4*)g_nv)[n0n * 96 + tid + 256 * i];
            }
        }

        ull oS[2] = {0ull, 0ull};
        ull oV[2][3] = {{0ull,0ull,0ull},{0ull,0ull,0ull}};
        for (int u = 0; u < 128; u += 2) {
            ulonglong2 wsp = *(const ulonglong2*)(sWsT + vt * 268 + u * 2);
            ulonglong2 wvp = *(const ulonglong2*)(sWvT + vt * 268 + u * 2);
#pragma unroll
            for (int k = 0; k < 2; k++) {
                int n = warp * 2 + k;
                float2 xs2 = *(const float2*)(sNs + n * 128 + u);
                oS[k] = ffma2(bcast2(xs2.x), wsp.x, oS[k]);
                oS[k] = ffma2(bcast2(xs2.y), wsp.y, oS[k]);
#pragma unroll
                for (int d = 0; d < 3; d++) {
                    float2 xv2 = *(const float2*)(sNv + n * 384 + d * 128 + u);
                    oV[k][d] = ffma2(bcast2(xv2.x), wvp.x, oV[k][d]);
                    oV[k][d] = ffma2(bcast2(xv2.y), wvp.y, oV[k][d]);
                }
            }
        }
        __syncthreads();   // GEMM reads of sNs/sNv done; epilogue is reg/global

#pragma unroll
        for (int k = 0; k < 2; k++) {
            const int n = n0 + warp * 2 + k;
            const float dn = rsqrtf(fmaxf(g_deg[n], 1.0f)) * inv2;
            float s0, s1;
            unpack2(oS[k], s0, s1);
            float2 scs = *(const float2*)(g_scs + n * 64 + vt * 2);
            s0 = s0 * dn + scs.x;
            s1 = s1 * dn + scs.y;
            float v0[3], v1[3];
            float vsum = 0.f;
#pragma unroll
            for (int d = 0; d < 3; d++) {
                float a, b;
                unpack2(oV[k][d], a, b);
                float2 scv = *(const float2*)(g_scv + n * 192 + d * 64 + vt * 2);
                a = a * dn + scv.x;
                b = b * dn + scv.y;
                v0[d] = a; v1[d] = b;
                vsum += a * a + b * b;
            }
            float ssum = s0 * s0 + s1 * s1;
#pragma unroll
            for (int off = 16; off; off >>= 1) {
                ssum += __shfl_xor_sync(0xffffffffu, ssum, off);
                vsum += __shfl_xor_sync(0xffffffffu, vsum, off);
            }
            const float rs = rsqrtf(ssum * (1.0f / 64.0f)  + 1e-5f);
            const float rv = rsqrtf(vsum * (1.0f / 192.0f) + 1e-5f);
            *(float2*)(out + n * 256 + vt * 2) =
                make_float2(s0 * rs * gs[vt * 2], s1 * rs * gs[vt * 2 + 1]);
            const float gv0 = gv[vt * 2] * rv, gv1 = gv[vt * 2 + 1] * rv;
#pragma unroll
            for (int d = 0; d < 3; d++) {
                out[n * 256 + 64 + (vt * 2)     * 3 + d] = v0[d] * gv0;
                out[n * 256 + 64 + (vt * 2 + 1) * 3 + d] = v1[d] * gv1;
            }
        }
    }
}

// ---------------- launcher ----------------------------------------------------
extern "C" void kernel_launch(void* const* d_in, const int* in_sizes, int n_in,
                              void* d_out, int out_size)
{
    const float* nh   = (const float*)d_in[0];
    const float* ea   = (const float*)d_in[1];
    const float* esh  = (const float*)d_in[2];
    const float* w1s  = (const float*)d_in[3];
    const float* w1v  = (const float*)d_in[4];
    const float* wscs = (const float*)d_in[5];
    const float* wscv = (const float*)d_in[6];
    const float* w2s  = (const float*)d_in[7];
    const float* w2v  = (const float*)d_in[8];
    const float* fw1  = (const float*)d_in[9];
    const float* fw2  = (const float*)d_in[10];
    const float* fw3  = (const float*)d_in[11];
    const float* gs   = (const float*)d_in[12];
    const float* gv   = (const float*)d_in[13];
    const int*   eidx = (const int*)d_in[14];
    float* out = (float*)d_out;

    cudaFuncSetAttribute(k_node_in,  cudaFuncAttributeMaxDynamicSharedMemorySize, K1_SMEM);
    cudaFuncSetAttribute(k_edge,     cudaFuncAttributeMaxDynamicSharedMemorySize, K2_SMEM);
    cudaFuncSetAttribute(k_node_out, cudaFuncAttributeMaxDynamicSharedMemorySize, K3_SMEM);

    k_node_in<<<296, 256, K1_SMEM>>>(nh, w1s, w1v, wscs, wscv);
    k_edge<<<148, 512, K2_SMEM>>>(ea, esh, eidx, fw1, fw2, fw3);
    k_node_out<<<296, 256, K3_SMEM>>>(w2s, w2v, gs, gv, out);
}